// round 6
// baseline (speedup 1.0000x reference)
#include <cuda_runtime.h>
#include <cuda_bf16.h>
#include <cstdint>

// Problem constants
#define B_   16
#define L_   1024
#define D_   512
#define H_   8
#define DK_  64
#define M_ROWS   (B_ * L_)            // 16384
#define TOK_ELEMS  (B_ * L_ * D_)     // 8388608
#define PROJ_ELEMS (B_ * H_ * L_ * DK_) // 8388608
#define OUT0_ELEMS ((size_t)B_ * L_ * D_)

// ---------------- scratch (device globals) ------------------------------------
// split activations (bf16 big/small): 0=sat_ln 1=ts_ln 2=satpos0 3=satpos1 4=tspos0 5=tspos1
__device__ __nv_bfloat16 g_Ab[6][TOK_ELEMS];
__device__ __nv_bfloat16 g_As[6][TOK_ELEMS];
// split transposed weights (K-major rows of 512): 0=Wq 1=Wk 2=Wsat 3=Wts
__device__ __nv_bfloat16 g_Wb[4][H_ * DK_ * D_];
__device__ __nv_bfloat16 g_Ws[4][H_ * DK_ * D_];
__device__ __nv_bfloat16 g_WVb[DK_ * D_];
__device__ __nv_bfloat16 g_WVs[DK_ * D_];

__device__ float g_q[PROJ_ELEMS];
__device__ float g_k[PROJ_ELEMS];
__device__ float g_ss[PROJ_ELEMS];
__device__ float g_cs[PROJ_ELEMS];
__device__ float g_st[PROJ_ELEMS];
__device__ float g_ct[PROJ_ELEMS];
__device__ float g_v[B_ * L_ * DK_];
__device__ float g_head[PROJ_ELEMS];

// ---------------- PTX helpers --------------------------------------------------
__device__ __forceinline__ uint32_t smem_u32(const void* p) {
    uint32_t a;
    asm("{ .reg .u64 t; cvta.to.shared.u64 t, %1; cvt.u32.u64 %0, t; }" : "=r"(a) : "l"(p));
    return a;
}
#define CP_ASYNC16(dst, src) \
    asm volatile("cp.async.cg.shared.global [%0], [%1], 16;" :: "r"(dst), "l"(src) : "memory")
#define CP_COMMIT() asm volatile("cp.async.commit_group;" ::: "memory")
#define CP_WAIT0()  asm volatile("cp.async.wait_group 0;" ::: "memory")
#define CP_WAIT1()  asm volatile("cp.async.wait_group 1;" ::: "memory")

#define LDSM_X4(r0, r1, r2, r3, addr) \
    asm volatile("ldmatrix.sync.aligned.m8n8.x4.shared.b16 {%0,%1,%2,%3}, [%4];" \
        : "=r"(r0), "=r"(r1), "=r"(r2), "=r"(r3) : "r"(addr))

#define MMA_BF16(c, a, b0, b1) \
    asm volatile("mma.sync.aligned.m16n8k16.row.col.f32.bf16.bf16.f32 " \
        "{%0,%1,%2,%3},{%4,%5,%6,%7},{%8,%9},{%0,%1,%2,%3};" \
        : "+f"((c)[0]), "+f"((c)[1]), "+f"((c)[2]), "+f"((c)[3]) \
        : "r"((a)[0]), "r"((a)[1]), "r"((a)[2]), "r"((a)[3]), "r"(b0), "r"(b1))

__device__ __forceinline__ void bf16_split(float x, __nv_bfloat16& big, __nv_bfloat16& sml) {
    big = __float2bfloat16_rn(x);
    sml = __float2bfloat16_rn(x - __bfloat162float(big));
}

// ---------------- LayerNorm (writes split bf16) --------------------------------
__global__ void ln_kernel(const float* __restrict__ sat, const float* __restrict__ ts,
                          const float* __restrict__ gs, const float* __restrict__ bs,
                          const float* __restrict__ gt, const float* __restrict__ bt)
{
    int rid = blockIdx.x;
    const float* src; __nv_bfloat16 *db, *ds; const float* g; const float* bb;
    if (rid < M_ROWS) {
        src = sat + (size_t)rid * D_;
        db = g_Ab[0] + (size_t)rid * D_;  ds = g_As[0] + (size_t)rid * D_;
        g = gs; bb = bs;
    } else {
        int r = rid - M_ROWS;
        src = ts + (size_t)r * D_;
        db = g_Ab[1] + (size_t)r * D_;    ds = g_As[1] + (size_t)r * D_;
        g = gt; bb = bt;
    }
    int t = threadIdx.x;
    float4 x = ((const float4*)src)[t];
    float s  = x.x + x.y + x.z + x.w;
    float sq = x.x*x.x + x.y*x.y + x.z*x.z + x.w*x.w;
    #pragma unroll
    for (int o = 16; o; o >>= 1) {
        s  += __shfl_xor_sync(0xFFFFFFFFu, s,  o);
        sq += __shfl_xor_sync(0xFFFFFFFFu, sq, o);
    }
    __shared__ float ws[4], wq[4];
    if ((t & 31) == 0) { ws[t >> 5] = s; wq[t >> 5] = sq; }
    __syncthreads();
    s  = ws[0] + ws[1] + ws[2] + ws[3];
    sq = wq[0] + wq[1] + wq[2] + wq[3];
    float m   = s * (1.0f / D_);
    float var = sq * (1.0f / D_) - m * m;
    float inv = rsqrtf(var + 1e-5f);
    float4 g4 = ((const float4*)g)[t];
    float4 b4 = ((const float4*)bb)[t];
    float o[4];
    o[0] = (x.x - m) * inv * g4.x + b4.x;
    o[1] = (x.y - m) * inv * g4.y + b4.y;
    o[2] = (x.z - m) * inv * g4.z + b4.z;
    o[3] = (x.w - m) * inv * g4.w + b4.w;
    __nv_bfloat16 big[4], sml[4];
    #pragma unroll
    for (int i = 0; i < 4; i++) bf16_split(o[i], big[i], sml[i]);
    *(uint2*)&db[t * 4] = *(uint2*)big;
    *(uint2*)&ds[t * 4] = *(uint2*)sml;
}

// ---------------- elementwise split (pos embeddings) ---------------------------
__global__ void split_kernel(const float* __restrict__ x, __nv_bfloat16* __restrict__ big,
                             __nv_bfloat16* __restrict__ sml)
{
    int i = blockIdx.x * blockDim.x + threadIdx.x;
    float4 v = ((const float4*)x)[i];
    __nv_bfloat16 b[4], s[4];
    bf16_split(v.x, b[0], s[0]);
    bf16_split(v.y, b[1], s[1]);
    bf16_split(v.z, b[2], s[2]);
    bf16_split(v.w, b[3], s[3]);
    *(uint2*)&big[(size_t)i * 4] = *(uint2*)b;
    *(uint2*)&sml[(size_t)i * 4] = *(uint2*)s;
}

// ---------------- weight transpose + split: (Hn,512,64) -> (Hn,64,512) ---------
__global__ void transpose_w(const float* __restrict__ W,
                            __nv_bfloat16* __restrict__ Wb, __nv_bfloat16* __restrict__ Wsml)
{
    __shared__ float t[64][65];
    int h = blockIdx.x, k0 = blockIdx.y * 64;
    const float* Wp = W + (size_t)h * (D_ * DK_);
    #pragma unroll
    for (int i = 0; i < 16; i++) {
        int e = threadIdx.x + i * 256;
        int r = e >> 6, c = e & 63;
        t[r][c] = Wp[(size_t)(k0 + r) * 64 + c];
    }
    __syncthreads();
    #pragma unroll
    for (int i = 0; i < 16; i++) {
        int e = threadIdx.x + i * 256;
        int n = e >> 6, kk = e & 63;
        __nv_bfloat16 big, sml;
        bf16_split(t[kk][n], big, sml);
        size_t off = (size_t)h * (DK_ * D_) + (size_t)n * 512 + k0 + kk;
        Wb[off] = big;
        Wsml[off] = sml;
    }
}

// ---------------- 3xBF16 mma.sync projection GEMM ------------------------------
// CTA tile 128x64, K chunk 32 (bf16), 2-stage cp.async pipeline, pre-split operands.
#define STRB 80                          // bytes per smem row (32 bf16 + pad)
#define ABSZ (128 * STRB)                // 10240
#define BBSZ (64 * STRB)                 // 5120
#define STAGE (2 * ABSZ + 2 * BBSZ)      // 30720
#define GEMM_SMEM (2 * STAGE)            // 61440

__global__ void __launch_bounds__(256) gemm_bf16(const __nv_bfloat16* __restrict__ Ab,
                                                 const __nv_bfloat16* __restrict__ As,
                                                 const __nv_bfloat16* __restrict__ Bb,
                                                 const __nv_bfloat16* __restrict__ Bs,
                                                 const float* __restrict__ bias,
                                                 float* __restrict__ C, int is_v)
{
    extern __shared__ __align__(16) char smraw[];
    uint32_t sb = smem_u32(smraw);
    int tid = threadIdx.x, lane = tid & 31, wid = tid >> 5;
    int warp_m = wid >> 1, warp_n = wid & 1;
    int m0 = blockIdx.x * 128, by = blockIdx.y, n0 = by * 64;

    // ldmatrix lane offsets (x4: matrices [r0-7,k0-7],[r8-15,k0-7],[r0-7,k8-15],[r8-15,k8-15])
    uint32_t laneA = (uint32_t)((warp_m * 32 + (lane & 7) + ((lane >> 3) & 1) * 8) * STRB + (lane >> 4) * 16);
    uint32_t laneB = (uint32_t)((warp_n * 32 + (lane & 7) + ((lane >> 3) & 1) * 8) * STRB + (lane >> 4) * 16);

    float c[8][4];
    #pragma unroll
    for (int i = 0; i < 8; i++)
        #pragma unroll
        for (int j = 0; j < 4; j++) c[i][j] = 0.0f;

    auto load_stage = [&](int s, int k0) {
        uint32_t base = sb + s * STAGE;
        #pragma unroll
        for (int i = 0; i < 2; i++) {
            int e = tid + i * 256, r = e >> 2, cc = e & 3;
            uint32_t d = base + (uint32_t)(r * STRB + cc * 16);
            const __nv_bfloat16* srcb = Ab + (size_t)(m0 + r) * 512 + k0 + cc * 8;
            const __nv_bfloat16* srcs = As + (size_t)(m0 + r) * 512 + k0 + cc * 8;
            CP_ASYNC16(d, srcb);
            CP_ASYNC16(d + ABSZ, srcs);
        }
        {
            int r = tid >> 2, cc = tid & 3;
            uint32_t d = base + 2 * ABSZ + (uint32_t)(r * STRB + cc * 16);
            const __nv_bfloat16* srcb = Bb + (size_t)(n0 + r) * 512 + k0 + cc * 8;
            const __nv_bfloat16* srcs = Bs + (size_t)(n0 + r) * 512 + k0 + cc * 8;
            CP_ASYNC16(d, srcb);
            CP_ASYNC16(d + BBSZ, srcs);
        }
    };

    auto compute = [&](int s) {
        uint32_t abB = sb + s * STAGE + laneA;
        uint32_t asB = abB + ABSZ;
        uint32_t bbB = sb + s * STAGE + 2 * ABSZ + laneB;
        uint32_t bsB = bbB + BBSZ;
        #pragma unroll
        for (int ks = 0; ks < 2; ks++) {
            uint32_t aB[2][4], aS[2][4], bB[2][4], bS[2][4];
            #pragma unroll
            for (int mt = 0; mt < 2; mt++) {
                LDSM_X4(aB[mt][0], aB[mt][1], aB[mt][2], aB[mt][3], abB + mt * (16 * STRB) + ks * 32);
                LDSM_X4(aS[mt][0], aS[mt][1], aS[mt][2], aS[mt][3], asB + mt * (16 * STRB) + ks * 32);
            }
            #pragma unroll
            for (int nt = 0; nt < 2; nt++) {
                LDSM_X4(bB[nt][0], bB[nt][1], bB[nt][2], bB[nt][3], bbB + nt * (16 * STRB) + ks * 32);
                LDSM_X4(bS[nt][0], bS[nt][1], bS[nt][2], bS[nt][3], bsB + nt * (16 * STRB) + ks * 32);
            }
            #pragma unroll
            for (int mt = 0; mt < 2; mt++)
                #pragma unroll
                for (int j = 0; j < 4; j++) {
                    int nt = j >> 1, h = j & 1;
                    float* cc = c[mt * 4 + j];
                    MMA_BF16(cc, aS[mt], bB[nt][h], bB[nt][2 + h]);
                    MMA_BF16(cc, aB[mt], bS[nt][h], bS[nt][2 + h]);
                    MMA_BF16(cc, aB[mt], bB[nt][h], bB[nt][2 + h]);
                }
        }
    };

    load_stage(0, 0);
    CP_COMMIT();
    for (int ck = 0; ck < 16; ck++) {
        if (ck < 15) {
            load_stage((ck + 1) & 1, (ck + 1) * 32);
            CP_COMMIT();
            CP_WAIT1();
        } else {
            CP_WAIT0();
        }
        __syncthreads();
        compute(ck & 1);
        __syncthreads();
    }

    int r_lane = lane >> 2, c_lane = (lane & 3) * 2;
    #pragma unroll
    for (int i = 0; i < 2; i++) {
        #pragma unroll
        for (int j = 0; j < 4; j++) {
            float* cc = c[i * 4 + j];
            int nc = warp_n * 32 + j * 8 + c_lane;
            int mrow = m0 + warp_m * 32 + i * 16 + r_lane;
            float2 bb2;
            size_t base0, base1;
            if (is_v) {
                bb2 = *(const float2*)&bias[nc];
                base0 = (size_t)mrow * 64 + nc;
                base1 = (size_t)(mrow + 8) * 64 + nc;
            } else {
                bb2 = *(const float2*)&bias[by * 64 + nc];
                int b0r = mrow >> 10, l0r = mrow & 1023;
                int b1r = (mrow + 8) >> 10, l1r = (mrow + 8) & 1023;
                base0 = ((((size_t)(b0r * 8 + by)) << 10) + l0r) * 64 + nc;
                base1 = ((((size_t)(b1r * 8 + by)) << 10) + l1r) * 64 + nc;
            }
            float2 o0 = {cc[0] + bb2.x, cc[1] + bb2.y};
            float2 o1 = {cc[2] + bb2.x, cc[3] + bb2.y};
            *(float2*)&C[base0] = o0;
            *(float2*)&C[base1] = o1;
        }
    }
}

// ---------------- RoPE --------------------------------------------------------
__global__ void rope_kernel()
{
    const int Np = PROJ_ELEMS / 2;
    int idx = blockIdx.x * blockDim.x + threadIdx.x;
    float2 *xb; const float2 *cb, *sb;
    if (idx < Np) {
        xb = (float2*)g_q; cb = (const float2*)g_ct; sb = (const float2*)g_st;
    } else {
        idx -= Np;
        xb = (float2*)g_k; cb = (const float2*)g_cs; sb = (const float2*)g_ss;
    }
    float2 x = xb[idx];
    float2 c = cb[idx];
    float2 s = sb[idx];
    float2 o;
    o.x = x.x * c.x - x.y * s.x;
    o.y = x.y * c.y + x.x * s.y;
    xb[idx] = o;
}

// ---------------- attention (R4 configuration: FFMA, QT=32) --------------------
#define QT  32
#define KT  256
#define SCP 1025
#define KVP 68
#define ATTN_SMEM_FLOATS (QT * SCP + KT * KVP + QT * 64)

__global__ void __launch_bounds__(256) attn_kernel(float* __restrict__ attn_out)
{
    extern __shared__ __align__(16) float smf[];
    float* sc = smf;
    float* kv = smf + QT * SCP;
    float* qs = kv + KT * KVP;

    int tid = threadIdx.x;
    int q0 = blockIdx.x * QT;
    int h  = blockIdx.y;
    int b  = blockIdx.z;
    size_t bh = (size_t)(b * H_ + h);

    size_t qbase = ((bh << 10) + q0) * 64;
    #pragma unroll
    for (int i = 0; i < 2; i++) {
        int e = tid + i * 256;
        ((float4*)qs)[e] = *(const float4*)&g_q[qbase + (size_t)e * 4];
    }

    int ty = tid >> 5, tx = tid & 31;

    for (int kt = 0; kt < 4; kt++) {
        __syncthreads();
        size_t kbase = ((bh << 10) + kt * KT) * 64;
        #pragma unroll
        for (int i = 0; i < 16; i++) {
            int e = tid + i * 256;
            int r = e >> 4, c4 = e & 15;
            float4 a = *(const float4*)&g_k[kbase + (size_t)r * 64 + c4 * 4];
            *(float4*)&kv[r * KVP + c4 * 4] = a;
        }
        __syncthreads();
        float acc[4][8];
        #pragma unroll
        for (int i = 0; i < 4; i++)
            #pragma unroll
            for (int j = 0; j < 8; j++) acc[i][j] = 0.0f;
        #pragma unroll
        for (int d = 0; d < 64; d += 4) {
            float4 a[4];
            #pragma unroll
            for (int i = 0; i < 4; i++) a[i] = *(float4*)&qs[(ty * 4 + i) * 64 + d];
            #pragma unroll
            for (int j = 0; j < 8; j++) {
                float4 bk = *(float4*)&kv[(tx + 32 * j) * KVP + d];
                #pragma unroll
                for (int i = 0; i < 4; i++)
                    acc[i][j] += a[i].x * bk.x + a[i].y * bk.y + a[i].z * bk.z + a[i].w * bk.w;
            }
        }
        #pragma unroll
        for (int i = 0; i < 4; i++)
            #pragma unroll
            for (int j = 0; j < 8; j++)
                sc[(ty * 4 + i) * SCP + kt * KT + tx + 32 * j] = acc[i][j] * 0.125f;
    }
    __syncthreads();

    for (int rr = ty * 4; rr < ty * 4 + 4; rr++) {
        float vals[32];
        float mx = -1e30f;
        #pragma unroll
        for (int j = 0; j < 32; j++) {
            vals[j] = sc[rr * SCP + tx + 32 * j];
            mx = fmaxf(mx, vals[j]);
        }
        #pragma unroll
        for (int o = 16; o; o >>= 1) mx = fmaxf(mx, __shfl_xor_sync(0xFFFFFFFFu, mx, o));
        float s = 0.0f;
        #pragma unroll
        for (int j = 0; j < 32; j++) { vals[j] = __expf(vals[j] - mx); s += vals[j]; }
        #pragma unroll
        for (int o = 16; o; o >>= 1) s += __shfl_xor_sync(0xFFFFFFFFu, s, o);
        float inv = 1.0f / s;
        size_t obase = (((size_t)(b * L_ + q0 + rr) * H_ + h) << 10);
        #pragma unroll
        for (int j = 0; j < 32; j++) {
            float p = vals[j] * inv;
            sc[rr * SCP + tx + 32 * j] = p;
            attn_out[obase + tx + 32 * j] = p;
        }
    }
    __syncthreads();

    int r0 = (tid & 7) * 4;
    int c0 = (tid >> 3) * 2;
    float hacc[4][2];
    #pragma unroll
    for (int i = 0; i < 4; i++) { hacc[i][0] = 0.0f; hacc[i][1] = 0.0f; }
    for (int vt = 0; vt < 4; vt++) {
        __syncthreads();
        size_t vbase = ((size_t)b * L_ + vt * KT) * 64;
        #pragma unroll
        for (int i = 0; i < 16; i++) {
            int e = tid + i * 256;
            int r = e >> 4, c4 = e & 15;
            float4 a = *(const float4*)&g_v[vbase + (size_t)r * 64 + c4 * 4];
            *(float4*)&kv[r * KVP + c4 * 4] = a;
        }
        __syncthreads();
        #pragma unroll 4
        for (int kk = 0; kk < KT; kk++) {
            float v0 = kv[kk * KVP + c0];
            float v1 = kv[kk * KVP + c0 + 1];
            #pragma unroll
            for (int i = 0; i < 4; i++) {
                float p = sc[(r0 + i) * SCP + vt * KT + kk];
                hacc[i][0] += p * v0;
                hacc[i][1] += p * v1;
            }
        }
    }
    #pragma unroll
    for (int i = 0; i < 4; i++) {
        size_t hb = ((bh << 10) + q0 + r0 + i) * 64 + c0;
        g_head[hb]     = hacc[i][0];
        g_head[hb + 1] = hacc[i][1];
    }
}

// ---------------- final: out = mean_h(head) @ Wh ------------------------------
__global__ void __launch_bounds__(256) out_kernel(const float* __restrict__ Wh,
                                                  float* __restrict__ out)
{
    extern __shared__ __align__(16) float sm2[];
    __shared__ float hm[8][64];
    int tid = threadIdx.x;
    int m0 = blockIdx.x * 8;
    int bb = m0 >> 10;
    int l0 = m0 & 1023;

    #pragma unroll
    for (int i = 0; i < 32; i++) {
        int e = tid + i * 256;
        ((float4*)sm2)[e] = ((const float4*)Wh)[e];
    }
    #pragma unroll
    for (int i = 0; i < 2; i++) {
        int e = tid + i * 256;
        int r = e >> 6, kk = e & 63;
        float s = 0.0f;
        #pragma unroll
        for (int hh = 0; hh < 8; hh++)
            s += g_head[(((size_t)(bb * H_ + hh) << 10) + l0 + r) * 64 + kk];
        hm[r][kk] = s * 0.125f;
    }
    __syncthreads();

    int ty = tid >> 6;
    int tx = tid & 63;
    float acc[2][8];
    #pragma unroll
    for (int i = 0; i < 2; i++)
        #pragma unroll
        for (int j = 0; j < 8; j++) acc[i][j] = 0.0f;
    #pragma unroll 8
    for (int d = 0; d < 64; d++) {
        float a0 = hm[ty * 2][d];
        float a1 = hm[ty * 2 + 1][d];
        float4 w0 = *(float4*)&sm2[d * 512 + tx * 8];
        float4 w1 = *(float4*)&sm2[d * 512 + tx * 8 + 4];
        acc[0][0] += a0 * w0.x; acc[0][1] += a0 * w0.y; acc[0][2] += a0 * w0.z; acc[0][3] += a0 * w0.w;
        acc[0][4] += a0 * w1.x; acc[0][5] += a0 * w1.y; acc[0][6] += a0 * w1.z; acc[0][7] += a0 * w1.w;
        acc[1][0] += a1 * w0.x; acc[1][1] += a1 * w0.y; acc[1][2] += a1 * w0.z; acc[1][3] += a1 * w0.w;
        acc[1][4] += a1 * w1.x; acc[1][5] += a1 * w1.y; acc[1][6] += a1 * w1.z; acc[1][7] += a1 * w1.w;
    }
    #pragma unroll
    for (int i = 0; i < 2; i++) {
        int m = m0 + ty * 2 + i;
        float4 o0 = {acc[i][0], acc[i][1], acc[i][2], acc[i][3]};
        float4 o1 = {acc[i][4], acc[i][5], acc[i][6], acc[i][7]};
        *(float4*)&out[(size_t)m * 512 + tx * 8]     = o0;
        *(float4*)&out[(size_t)m * 512 + tx * 8 + 4] = o1;
    }
}

// ---------------- launch ------------------------------------------------------
extern "C" void kernel_launch(void* const* d_in, const int* in_sizes, int n_in,
                              void* d_out, int out_size)
{
    const float* sat     = (const float*)d_in[0];
    const float* satpos  = (const float*)d_in[1];
    const float* ts      = (const float*)d_in[2];
    const float* tspos   = (const float*)d_in[3];
    const float* lsg     = (const float*)d_in[4];
    const float* lsb     = (const float*)d_in[5];
    const float* ltg     = (const float*)d_in[6];
    const float* ltb     = (const float*)d_in[7];
    const float* Wv      = (const float*)d_in[8];
    const float* bv      = (const float*)d_in[9];
    const float* Wq      = (const float*)d_in[10];
    const float* bq      = (const float*)d_in[11];
    const float* Wk      = (const float*)d_in[12];
    const float* bk      = (const float*)d_in[13];
    const float* Wsat    = (const float*)d_in[14];
    const float* bsat    = (const float*)d_in[15];
    const float* Wts     = (const float*)d_in[16];
    const float* bts     = (const float*)d_in[17];
    const float* Wh      = (const float*)d_in[18];

    float* out      = (float*)d_out;
    float* attn_out = out + OUT0_ELEMS;

    float *p_q, *p_k, *p_ss, *p_cs, *p_st, *p_ct, *p_v;
    __nv_bfloat16 *p_Ab, *p_As, *p_Wb, *p_Ws, *p_WVb, *p_WVs;
    cudaGetSymbolAddress((void**)&p_q,   g_q);
    cudaGetSymbolAddress((void**)&p_k,   g_k);
    cudaGetSymbolAddress((void**)&p_ss,  g_ss);
    cudaGetSymbolAddress((void**)&p_cs,  g_cs);
    cudaGetSymbolAddress((void**)&p_st,  g_st);
    cudaGetSymbolAddress((void**)&p_ct,  g_ct);
    cudaGetSymbolAddress((void**)&p_v,   g_v);
    cudaGetSymbolAddress((void**)&p_Ab,  g_Ab);
    cudaGetSymbolAddress((void**)&p_As,  g_As);
    cudaGetSymbolAddress((void**)&p_Wb,  g_Wb);
    cudaGetSymbolAddress((void**)&p_Ws,  g_Ws);
    cudaGetSymbolAddress((void**)&p_WVb, g_WVb);
    cudaGetSymbolAddress((void**)&p_WVs, g_WVs);

    const int attn_smem = ATTN_SMEM_FLOATS * 4;   // 209024
    cudaFuncSetAttribute(attn_kernel, cudaFuncAttributeMaxDynamicSharedMemorySize, attn_smem);
    cudaFuncSetAttribute(out_kernel,  cudaFuncAttributeMaxDynamicSharedMemorySize, 64 * 512 * 4);
    cudaFuncSetAttribute(gemm_bf16,   cudaFuncAttributeMaxDynamicSharedMemorySize, GEMM_SMEM);

    const size_t WSZ = (size_t)H_ * DK_ * D_;

    // 1. LayerNorms (emit split bf16)
    ln_kernel<<<2 * M_ROWS, 128>>>(sat, ts, lsg, lsb, ltg, ltb);

    // 2. split pos embeddings
    split_kernel<<<TOK_ELEMS / 1024, 256>>>(satpos,              p_Ab + 2 * (size_t)TOK_ELEMS, p_As + 2 * (size_t)TOK_ELEMS);
    split_kernel<<<TOK_ELEMS / 1024, 256>>>(satpos + TOK_ELEMS,  p_Ab + 3 * (size_t)TOK_ELEMS, p_As + 3 * (size_t)TOK_ELEMS);
    split_kernel<<<TOK_ELEMS / 1024, 256>>>(tspos,               p_Ab + 4 * (size_t)TOK_ELEMS, p_As + 4 * (size_t)TOK_ELEMS);
    split_kernel<<<TOK_ELEMS / 1024, 256>>>(tspos + TOK_ELEMS,   p_Ab + 5 * (size_t)TOK_ELEMS, p_As + 5 * (size_t)TOK_ELEMS);

    // 3. transpose + split weights
    transpose_w<<<dim3(8, 8), 256>>>(Wq,   p_Wb + 0 * WSZ, p_Ws + 0 * WSZ);
    transpose_w<<<dim3(8, 8), 256>>>(Wk,   p_Wb + 1 * WSZ, p_Ws + 1 * WSZ);
    transpose_w<<<dim3(8, 8), 256>>>(Wsat, p_Wb + 2 * WSZ, p_Ws + 2 * WSZ);
    transpose_w<<<dim3(8, 8), 256>>>(Wts,  p_Wb + 3 * WSZ, p_Ws + 3 * WSZ);
    transpose_w<<<dim3(1, 8), 256>>>(Wv,   p_WVb, p_WVs);

    // 4. 3xBF16 projections
    dim3 gg(M_ROWS / 128, 8);
    const size_t TE = (size_t)TOK_ELEMS;
    gemm_bf16<<<gg, 256, GEMM_SMEM>>>(p_Ab + 1 * TE, p_As + 1 * TE, p_Wb + 0 * WSZ, p_Ws + 0 * WSZ, bq,   p_q,  0);
    gemm_bf16<<<gg, 256, GEMM_SMEM>>>(p_Ab + 0 * TE, p_As + 0 * TE, p_Wb + 1 * WSZ, p_Ws + 1 * WSZ, bk,   p_k,  0);
    gemm_bf16<<<gg, 256, GEMM_SMEM>>>(p_Ab + 2 * TE, p_As + 2 * TE, p_Wb + 2 * WSZ, p_Ws + 2 * WSZ, bsat, p_ss, 0);
    gemm_bf16<<<gg, 256, GEMM_SMEM>>>(p_Ab + 3 * TE, p_As + 3 * TE, p_Wb + 2 * WSZ, p_Ws + 2 * WSZ, bsat, p_cs, 0);
    gemm_bf16<<<gg, 256, GEMM_SMEM>>>(p_Ab + 4 * TE, p_As + 4 * TE, p_Wb + 3 * WSZ, p_Ws + 3 * WSZ, bts,  p_st, 0);
    gemm_bf16<<<gg, 256, GEMM_SMEM>>>(p_Ab + 5 * TE, p_As + 5 * TE, p_Wb + 3 * WSZ, p_Ws + 3 * WSZ, bts,  p_ct, 0);
    gemm_bf16<<<dim3(M_ROWS / 128, 1), 256, GEMM_SMEM>>>(p_Ab + 0 * TE, p_As + 0 * TE, p_WVb, p_WVs, bv, p_v, 1);

    // 5. RoPE
    rope_kernel<<<PROJ_ELEMS / 256, 256>>>();

    // 6. attention (R4 config)
    dim3 ga(L_ / QT, H_, B_);
    attn_kernel<<<ga, 256, attn_smem>>>(attn_out);

    // 7. out = mean_h(head) @ Wh
    out_kernel<<<M_ROWS / 8, 256, 64 * 512 * 4>>>(Wh, out);
}

// round 8
// speedup vs baseline: 1.4799x; 1.4799x over previous
#include <cuda_runtime.h>
#include <cuda_bf16.h>
#include <cstdint>

// Problem constants
#define B_   16
#define L_   1024
#define D_   512
#define H_   8
#define DK_  64
#define M_ROWS   (B_ * L_)            // 16384
#define TOK_ELEMS  (B_ * L_ * D_)     // 8388608
#define PROJ_ELEMS (B_ * H_ * L_ * DK_) // 8388608
#define OUT0_ELEMS ((size_t)B_ * L_ * D_)

// ---------------- scratch (device globals) ------------------------------------
__device__ float g_sat_ln[TOK_ELEMS];
__device__ float g_ts_ln[TOK_ELEMS];
__device__ float g_q[PROJ_ELEMS];
__device__ float g_k[PROJ_ELEMS];
__device__ float g_ss[PROJ_ELEMS];
__device__ float g_cs[PROJ_ELEMS];
__device__ float g_st[PROJ_ELEMS];
__device__ float g_ct[PROJ_ELEMS];
__device__ float g_v[B_ * L_ * DK_];
__device__ float g_head[PROJ_ELEMS];
// transposed weights (K-major rows of length 512): (H, DK, D)
__device__ float g_WtQ[H_ * DK_ * D_];
__device__ float g_WtK[H_ * DK_ * D_];
__device__ float g_WtSat[H_ * DK_ * D_];
__device__ float g_WtTs[H_ * DK_ * D_];
__device__ float g_WtV[DK_ * D_];
// post-RoPE q/k as split bf16 (big + small) for tensor-core QK^T
__device__ __nv_bfloat16 g_qb[PROJ_ELEMS];
__device__ __nv_bfloat16 g_qs[PROJ_ELEMS];
__device__ __nv_bfloat16 g_kb[PROJ_ELEMS];
__device__ __nv_bfloat16 g_ks[PROJ_ELEMS];

// ---------------- PTX helpers (portable: compute_80+) --------------------------
__device__ __forceinline__ uint32_t smem_u32(const void* p) {
    uint32_t a;
    asm("{ .reg .u64 t; cvta.to.shared.u64 t, %1; cvt.u32.u64 %0, t; }" : "=r"(a) : "l"(p));
    return a;
}
#define CP_ASYNC16(dst, src) \
    asm volatile("cp.async.cg.shared.global [%0], [%1], 16;" :: "r"(dst), "l"(src) : "memory")
#define CP_COMMIT() asm volatile("cp.async.commit_group;" ::: "memory")
#define CP_WAIT0()  asm volatile("cp.async.wait_group 0;" ::: "memory")
#define CP_WAIT1()  asm volatile("cp.async.wait_group 1;" ::: "memory")

#define LDSM_X4(r0, r1, r2, r3, addr) \
    asm volatile("ldmatrix.sync.aligned.m8n8.x4.shared.b16 {%0,%1,%2,%3}, [%4];" \
        : "=r"(r0), "=r"(r1), "=r"(r2), "=r"(r3) : "r"(addr))

#define MMA_TF32(c, a0, a1, a2, a3, b0, b1) \
    asm volatile("mma.sync.aligned.m16n8k8.row.col.f32.tf32.tf32.f32 " \
        "{%0,%1,%2,%3},{%4,%5,%6,%7},{%8,%9},{%0,%1,%2,%3};" \
        : "+f"((c)[0]), "+f"((c)[1]), "+f"((c)[2]), "+f"((c)[3]) \
        : "r"(a0), "r"(a1), "r"(a2), "r"(a3), "r"(b0), "r"(b1))

#define MMA_BF16(c, a0, a1, a2, a3, b0, b1) \
    asm volatile("mma.sync.aligned.m16n8k16.row.col.f32.bf16.bf16.f32 " \
        "{%0,%1,%2,%3},{%4,%5,%6,%7},{%8,%9},{%0,%1,%2,%3};" \
        : "+f"((c)[0]), "+f"((c)[1]), "+f"((c)[2]), "+f"((c)[3]) \
        : "r"(a0), "r"(a1), "r"(a2), "r"(a3), "r"(b0), "r"(b1))

__device__ __forceinline__ void tf32_split(uint32_t x, uint32_t& big, uint32_t& sml) {
    float xf = __uint_as_float(x);
    asm("cvt.rna.tf32.f32 %0, %1;" : "=r"(big) : "f"(xf));
    float r = xf - __uint_as_float(big);
    asm("cvt.rna.tf32.f32 %0, %1;" : "=r"(sml) : "f"(r));
}
__device__ __forceinline__ void bf16_split(float x, __nv_bfloat16& big, __nv_bfloat16& sml) {
    big = __float2bfloat16_rn(x);
    sml = __float2bfloat16_rn(x - __bfloat162float(big));
}

// ---------------- LayerNorm ---------------------------------------------------
__global__ void ln_kernel(const float* __restrict__ sat, const float* __restrict__ ts,
                          const float* __restrict__ gs, const float* __restrict__ bs,
                          const float* __restrict__ gt, const float* __restrict__ bt)
{
    int rid = blockIdx.x;
    const float* src; float* dst; const float* g; const float* bb;
    if (rid < M_ROWS) {
        src = sat + (size_t)rid * D_; dst = g_sat_ln + (size_t)rid * D_; g = gs; bb = bs;
    } else {
        int r = rid - M_ROWS;
        src = ts + (size_t)r * D_;   dst = g_ts_ln + (size_t)r * D_;  g = gt; bb = bt;
    }
    int t = threadIdx.x;
    float4 x = ((const float4*)src)[t];
    float s  = x.x + x.y + x.z + x.w;
    float sq = x.x*x.x + x.y*x.y + x.z*x.z + x.w*x.w;
    #pragma unroll
    for (int o = 16; o; o >>= 1) {
        s  += __shfl_xor_sync(0xFFFFFFFFu, s,  o);
        sq += __shfl_xor_sync(0xFFFFFFFFu, sq, o);
    }
    __shared__ float ws[4], wq[4];
    if ((t & 31) == 0) { ws[t >> 5] = s; wq[t >> 5] = sq; }
    __syncthreads();
    s  = ws[0] + ws[1] + ws[2] + ws[3];
    sq = wq[0] + wq[1] + wq[2] + wq[3];
    float m   = s * (1.0f / D_);
    float var = sq * (1.0f / D_) - m * m;
    float inv = rsqrtf(var + 1e-5f);
    float4 g4 = ((const float4*)g)[t];
    float4 b4 = ((const float4*)bb)[t];
    float4 o;
    o.x = (x.x - m) * inv * g4.x + b4.x;
    o.y = (x.y - m) * inv * g4.y + b4.y;
    o.z = (x.z - m) * inv * g4.z + b4.z;
    o.w = (x.w - m) * inv * g4.w + b4.w;
    ((float4*)dst)[t] = o;
}

// ---------------- weight transpose: W (Hn,512,64) -> Wt (Hn,64,512) -----------
__global__ void transpose_w(const float* __restrict__ W, float* __restrict__ Wt)
{
    __shared__ float t[64][65];
    int h = blockIdx.x, k0 = blockIdx.y * 64;
    const float* Wp = W + (size_t)h * (D_ * DK_);
    float* Wo = Wt + (size_t)h * (DK_ * D_);
    #pragma unroll
    for (int i = 0; i < 16; i++) {
        int e = threadIdx.x + i * 256;
        int r = e >> 6, c = e & 63;
        t[r][c] = Wp[(size_t)(k0 + r) * 64 + c];
    }
    __syncthreads();
    #pragma unroll
    for (int i = 0; i < 16; i++) {
        int e = threadIdx.x + i * 256;
        int n = e >> 6, kk = e & 63;
        Wo[(size_t)n * 512 + k0 + kk] = t[kk][n];
    }
}

// ---------------- 3xTF32 mma.sync projection GEMM (proven R4) ------------------
#define ASTRIDE 36
#define ASZ (128 * ASTRIDE * 4)
#define BSZ (64  * ASTRIDE * 4)
#define STG (ASZ + BSZ)
#define GEMM_SMEM (2 * STG)              // 55296 B

__global__ void __launch_bounds__(256) gemm_mma(const float* __restrict__ A,
                                                const float* __restrict__ Bt,
                                                const float* __restrict__ bias,
                                                float* __restrict__ C,
                                                int is_v)
{
    extern __shared__ __align__(16) char smraw[];
    uint32_t sb = smem_u32(smraw);
    int tid = threadIdx.x;
    int lane = tid & 31, wid = tid >> 5;
    int warp_m = wid >> 1, warp_n = wid & 1;
    int m0 = blockIdx.x * 128, by = blockIdx.y, n0 = by * 64;

    int t8 = lane & 7, sel = lane >> 3;
    uint32_t aOff = (uint32_t)(((warp_m * 32 + (sel & 1) * 8 + t8) * ASTRIDE + (sel >> 1) * 4) * 4);
    uint32_t bOff = (uint32_t)(((warp_n * 32 + (sel >> 1) * 8 + t8) * ASTRIDE + (sel & 1) * 4) * 4);

    float c[8][4];
    #pragma unroll
    for (int i = 0; i < 8; i++)
        #pragma unroll
        for (int j = 0; j < 4; j++) c[i][j] = 0.0f;

    auto load_stage = [&](int s, int k0) {
        uint32_t ab = sb + s * STG, bbs = ab + ASZ;
        #pragma unroll
        for (int i = 0; i < 4; i++) {
            int e = tid + i * 256, r = e >> 3, c4 = e & 7;
            CP_ASYNC16(ab + (uint32_t)((r * ASTRIDE + c4 * 4) * 4),
                       A + (size_t)(m0 + r) * 512 + k0 + c4 * 4);
        }
        #pragma unroll
        for (int i = 0; i < 2; i++) {
            int e = tid + i * 256, r = e >> 3, c4 = e & 7;
            CP_ASYNC16(bbs + (uint32_t)((r * ASTRIDE + c4 * 4) * 4),
                       Bt + (size_t)(n0 + r) * 512 + k0 + c4 * 4);
        }
    };

    auto compute = [&](int s) {
        uint32_t ab = sb + s * STG + aOff;
        uint32_t bb = sb + s * STG + ASZ + bOff;
        #pragma unroll
        for (int ks = 0; ks < 4; ks++) {
            uint32_t a[8], b[8];
            LDSM_X4(a[0], a[1], a[2], a[3], ab + ks * 32);
            LDSM_X4(a[4], a[5], a[6], a[7], ab + (uint32_t)(16 * ASTRIDE * 4) + ks * 32);
            LDSM_X4(b[0], b[1], b[2], b[3], bb + ks * 32);
            LDSM_X4(b[4], b[5], b[6], b[7], bb + (uint32_t)(16 * ASTRIDE * 4) + ks * 32);
            uint32_t aB[8], aS[8], bB[8], bS[8];
            #pragma unroll
            for (int i = 0; i < 8; i++) { tf32_split(a[i], aB[i], aS[i]); tf32_split(b[i], bB[i], bS[i]); }
            #pragma unroll
            for (int i = 0; i < 2; i++)
                #pragma unroll
                for (int j = 0; j < 4; j++) {
                    float* cc = c[i * 4 + j];
                    MMA_TF32(cc, aS[i*4], aS[i*4+1], aS[i*4+2], aS[i*4+3], bB[j*2], bB[j*2+1]);
                    MMA_TF32(cc, aB[i*4], aB[i*4+1], aB[i*4+2], aB[i*4+3], bS[j*2], bS[j*2+1]);
                    MMA_TF32(cc, aB[i*4], aB[i*4+1], aB[i*4+2], aB[i*4+3], bB[j*2], bB[j*2+1]);
                }
        }
    };

    load_stage(0, 0);
    CP_COMMIT();
    for (int ck = 0; ck < 16; ck++) {
        if (ck < 15) {
            load_stage((ck + 1) & 1, (ck + 1) * 32);
            CP_COMMIT();
            CP_WAIT1();
        } else {
            CP_WAIT0();
        }
        __syncthreads();
        compute(ck & 1);
        __syncthreads();
    }

    int r_lane = lane >> 2, c_lane = (lane & 3) * 2;
    #pragma unroll
    for (int i = 0; i < 2; i++) {
        #pragma unroll
        for (int j = 0; j < 4; j++) {
            float* cc = c[i * 4 + j];
            int nc = warp_n * 32 + j * 8 + c_lane;
            int mrow = m0 + warp_m * 32 + i * 16 + r_lane;
            float2 bb2;
            size_t base0, base1;
            if (is_v) {
                bb2 = *(const float2*)&bias[nc];
                base0 = (size_t)mrow * 64 + nc;
                base1 = (size_t)(mrow + 8) * 64 + nc;
            } else {
                bb2 = *(const float2*)&bias[by * 64 + nc];
                int b0r = mrow >> 10, l0r = mrow & 1023;
                int b1r = (mrow + 8) >> 10, l1r = (mrow + 8) & 1023;
                base0 = ((((size_t)(b0r * 8 + by)) << 10) + l0r) * 64 + nc;
                base1 = ((((size_t)(b1r * 8 + by)) << 10) + l1r) * 64 + nc;
            }
            float2 o0 = {cc[0] + bb2.x, cc[1] + bb2.y};
            float2 o1 = {cc[2] + bb2.x, cc[3] + bb2.y};
            *(float2*)&C[base0] = o0;
            *(float2*)&C[base1] = o1;
        }
    }
}

// ---------------- RoPE (emits split bf16 q/k for tensor QK^T) ------------------
__global__ void rope_kernel()
{
    const int Np = PROJ_ELEMS / 2;
    int idx = blockIdx.x * blockDim.x + threadIdx.x;
    const float2 *xb, *cb, *sb; __nv_bfloat162 *ob, *os;
    if (idx < Np) {
        xb = (const float2*)g_q; cb = (const float2*)g_ct; sb = (const float2*)g_st;
        ob = (__nv_bfloat162*)g_qb; os = (__nv_bfloat162*)g_qs;
    } else {
        idx -= Np;
        xb = (const float2*)g_k; cb = (const float2*)g_cs; sb = (const float2*)g_ss;
        ob = (__nv_bfloat162*)g_kb; os = (__nv_bfloat162*)g_ks;
    }
    float2 x = xb[idx];
    float2 c = cb[idx];
    float2 s = sb[idx];
    float ox = x.x * c.x - x.y * s.x;
    float oy = x.y * c.y + x.x * s.y;
    __nv_bfloat16 b0, s0, b1, s1;
    bf16_split(ox, b0, s0);
    bf16_split(oy, b1, s1);
    __nv_bfloat162 vb; vb.x = b0; vb.y = b1;
    __nv_bfloat162 vs; vs.x = s0; vs.y = s1;
    ob[idx] = vb;
    os[idx] = vs;
}

// ---------------- attention: bf16x3 tensor QK^T + FFMA PV ----------------------
#define QT  32
#define KT  256
#define SCP 1025
#define KVP 68
#define STRK 144                          // bytes per bf16 smem row (128B data + 16 pad)
// byte layout: sc [0,131200) | K/V region [131200, 204928) | q [204928, 214144)
#define SC_BYTES   (QT * SCP * 4)         // 131200
#define KREG_OFF   SC_BYTES
#define KREG_BYTES (2 * KT * STRK)        // 73728 (Kb | Ks); V fp32 (69632) reuses it
#define QREG_OFF   (KREG_OFF + KREG_BYTES)
#define QB_BYTES   (QT * STRK)            // 4608
#define ATTN_SMEM  (QREG_OFF + 2 * QB_BYTES)   // 214144

__global__ void __launch_bounds__(256) attn_kernel(float* __restrict__ attn_out)
{
    extern __shared__ __align__(16) float smf[];
    float* sc  = smf;
    char*  kreg = (char*)smf + KREG_OFF;
    char*  qreg = (char*)smf + QREG_OFF;
    float* kvf = (float*)kreg;            // V phase view (KVP stride)

    int tid = threadIdx.x, lane = tid & 31, wid = tid >> 5;
    int q0 = blockIdx.x * QT;
    int h  = blockIdx.y;
    int b  = blockIdx.z;
    size_t bh = (size_t)(b * H_ + h);

    uint32_t skb = smem_u32(kreg), sqb = smem_u32(qreg);

    // load q tile (32 rows x 64 bf16, big + small), 16B chunks
    {
        int r = tid >> 3, cch = tid & 7;   // 256 threads = 32 rows x 8 chunks
        const uint4* srcb = (const uint4*)&g_qb[((bh << 10) + q0 + r) * 64];
        const uint4* srcs = (const uint4*)&g_qs[((bh << 10) + q0 + r) * 64];
        *(uint4*)(qreg + r * STRK + cch * 16)            = srcb[cch];
        *(uint4*)(qreg + QB_BYTES + r * STRK + cch * 16) = srcs[cch];
    }

    // fragment lane offsets
    uint32_t aB0 = sqb + (uint32_t)(((lane & 7) + ((lane >> 3) & 1) * 8) * STRK + (lane >> 4) * 16);
    uint32_t aS0 = aB0 + QB_BYTES;
    uint32_t bB0 = skb + (uint32_t)((wid * 32 + (lane & 7) + ((lane >> 3) & 1) * 8) * STRK + (lane >> 4) * 16);
    uint32_t bS0 = bB0 + (uint32_t)(KT * STRK);

    // ---- scores: 4 chunks of 256 keys; warp wid covers keys [wid*32, wid*32+31] ----
    for (int kt = 0; kt < 4; kt++) {
        __syncthreads();
        size_t kbase = ((bh << 10) + kt * KT) * 64;
        #pragma unroll
        for (int i = 0; i < 8; i++) {
            int e = tid + i * 256, r = e >> 3, cch = e & 7;   // 2048 chunks per array
            const uint4* srcb = (const uint4*)&g_kb[kbase + (size_t)r * 64];
            const uint4* srcs = (const uint4*)&g_ks[kbase + (size_t)r * 64];
            *(uint4*)(kreg + r * STRK + cch * 16)             = srcb[cch];
            *(uint4*)(kreg + KT * STRK + r * STRK + cch * 16) = srcs[cch];
        }
        __syncthreads();

        float c[2][4][4];
        #pragma unroll
        for (int mt = 0; mt < 2; mt++)
            #pragma unroll
            for (int j = 0; j < 4; j++)
                #pragma unroll
                for (int e = 0; e < 4; e++) c[mt][j][e] = 0.0f;

        #pragma unroll
        for (int ks = 0; ks < 4; ks++) {
            uint32_t aB[2][4], aS[2][4], bB[2][4], bS[2][4];
            #pragma unroll
            for (int mt = 0; mt < 2; mt++) {
                LDSM_X4(aB[mt][0], aB[mt][1], aB[mt][2], aB[mt][3], aB0 + mt * (16 * STRK) + ks * 32);
                LDSM_X4(aS[mt][0], aS[mt][1], aS[mt][2], aS[mt][3], aS0 + mt * (16 * STRK) + ks * 32);
            }
            #pragma unroll
            for (int nt = 0; nt < 2; nt++) {
                LDSM_X4(bB[nt][0], bB[nt][1], bB[nt][2], bB[nt][3], bB0 + nt * (16 * STRK) + ks * 32);
                LDSM_X4(bS[nt][0], bS[nt][1], bS[nt][2], bS[nt][3], bS0 + nt * (16 * STRK) + ks * 32);
            }
            #pragma unroll
            for (int mt = 0; mt < 2; mt++)
                #pragma unroll
                for (int j = 0; j < 4; j++) {
                    int nt = j >> 1, hh = j & 1;
                    float* cc = c[mt][j];
                    MMA_BF16(cc, aS[mt][0], aS[mt][1], aS[mt][2], aS[mt][3], bB[nt][hh], bB[nt][2 + hh]);
                    MMA_BF16(cc, aB[mt][0], aB[mt][1], aB[mt][2], aB[mt][3], bS[nt][hh], bS[nt][2 + hh]);
                    MMA_BF16(cc, aB[mt][0], aB[mt][1], aB[mt][2], aB[mt][3], bB[nt][hh], bB[nt][2 + hh]);
                }
        }
        // write scores (SCALAR stores: SCP is odd, float2 would be misaligned)
        int rr = lane >> 2, ccl = (lane & 3) * 2;
        #pragma unroll
        for (int mt = 0; mt < 2; mt++)
            #pragma unroll
            for (int j = 0; j < 4; j++) {
                int col = kt * KT + wid * 32 + j * 8 + ccl;
                int row0 = mt * 16 + rr;
                sc[row0 * SCP + col]           = c[mt][j][0] * 0.125f;
                sc[row0 * SCP + col + 1]       = c[mt][j][1] * 0.125f;
                sc[(row0 + 8) * SCP + col]     = c[mt][j][2] * 0.125f;
                sc[(row0 + 8) * SCP + col + 1] = c[mt][j][3] * 0.125f;
            }
    }
    __syncthreads();

    // ---- softmax: warp wid owns rows wid*4 .. wid*4+3 ----
    for (int rr = wid * 4; rr < wid * 4 + 4; rr++) {
        float vals[32];
        float mx = -1e30f;
        #pragma unroll
        for (int j = 0; j < 32; j++) {
            vals[j] = sc[rr * SCP + lane + 32 * j];
            mx = fmaxf(mx, vals[j]);
        }
        #pragma unroll
        for (int o = 16; o; o >>= 1) mx = fmaxf(mx, __shfl_xor_sync(0xFFFFFFFFu, mx, o));
        float s = 0.0f;
        #pragma unroll
        for (int j = 0; j < 32; j++) { vals[j] = __expf(vals[j] - mx); s += vals[j]; }
        #pragma unroll
        for (int o = 16; o; o >>= 1) s += __shfl_xor_sync(0xFFFFFFFFu, s, o);
        float inv = 1.0f / s;
        size_t obase = (((size_t)(b * L_ + q0 + rr) * H_ + h) << 10);
        #pragma unroll
        for (int j = 0; j < 32; j++) {
            float p = vals[j] * inv;
            sc[rr * SCP + lane + 32 * j] = p;
            attn_out[obase + lane + 32 * j] = p;
        }
    }
    __syncthreads();

    // ---- head = P @ V (FFMA; thread tile 4 rows x 2 cols) ----
    int r0 = (tid & 7) * 4;
    int c0 = (tid >> 3) * 2;
    float hacc[4][2];
    #pragma unroll
    for (int i = 0; i < 4; i++) { hacc[i][0] = 0.0f; hacc[i][1] = 0.0f; }
    for (int vt = 0; vt < 4; vt++) {
        __syncthreads();
        size_t vbase = ((size_t)b * L_ + vt * KT) * 64;
        #pragma unroll
        for (int i = 0; i < 16; i++) {
            int e = tid + i * 256;
            int r = e >> 4, c4 = e & 15;
            float4 a = *(const float4*)&g_v[vbase + (size_t)r * 64 + c4 * 4];
            *(float4*)&kvf[r * KVP + c4 * 4] = a;
        }
        __syncthreads();
        #pragma unroll 4
        for (int kk = 0; kk < KT; kk++) {
            float v0 = kvf[kk * KVP + c0];
            float v1 = kvf[kk * KVP + c0 + 1];
            #pragma unroll
            for (int i = 0; i < 4; i++) {
                float p = sc[(r0 + i) * SCP + vt * KT + kk];
                hacc[i][0] += p * v0;
                hacc[i][1] += p * v1;
            }
        }
    }
    #pragma unroll
    for (int i = 0; i < 4; i++) {
        size_t hb = ((bh << 10) + q0 + r0 + i) * 64 + c0;
        g_head[hb]     = hacc[i][0];
        g_head[hb + 1] = hacc[i][1];
    }
}

// ---------------- final: out = mean_h(head) @ Wh ------------------------------
__global__ void __launch_bounds__(256) out_kernel(const float* __restrict__ Wh,
                                                  float* __restrict__ out)
{
    extern __shared__ __align__(16) float sm2[];
    __shared__ float hm[8][64];
    int tid = threadIdx.x;
    int m0 = blockIdx.x * 8;
    int bb = m0 >> 10;
    int l0 = m0 & 1023;

    #pragma unroll
    for (int i = 0; i < 32; i++) {
        int e = tid + i * 256;
        ((float4*)sm2)[e] = ((const float4*)Wh)[e];
    }
    #pragma unroll
    for (int i = 0; i < 2; i++) {
        int e = tid + i * 256;
        int r = e >> 6, kk = e & 63;
        float s = 0.0f;
        #pragma unroll
        for (int hh = 0; hh < 8; hh++)
            s += g_head[(((size_t)(bb * H_ + hh) << 10) + l0 + r) * 64 + kk];
        hm[r][kk] = s * 0.125f;
    }
    __syncthreads();

    int ty = tid >> 6;
    int tx = tid & 63;
    float acc[2][8];
    #pragma unroll
    for (int i = 0; i < 2; i++)
        #pragma unroll
        for (int j = 0; j < 8; j++) acc[i][j] = 0.0f;
    #pragma unroll 8
    for (int d = 0; d < 64; d++) {
        float a0 = hm[ty * 2][d];
        float a1 = hm[ty * 2 + 1][d];
        float4 w0 = *(float4*)&sm2[d * 512 + tx * 8];
        float4 w1 = *(float4*)&sm2[d * 512 + tx * 8 + 4];
        acc[0][0] += a0 * w0.x; acc[0][1] += a0 * w0.y; acc[0][2] += a0 * w0.z; acc[0][3] += a0 * w0.w;
        acc[0][4] += a0 * w1.x; acc[0][5] += a0 * w1.y; acc[0][6] += a0 * w1.z; acc[0][7] += a0 * w1.w;
        acc[1][0] += a1 * w0.x; acc[1][1] += a1 * w0.y; acc[1][2] += a1 * w0.z; acc[1][3] += a1 * w0.w;
        acc[1][4] += a1 * w1.x; acc[1][5] += a1 * w1.y; acc[1][6] += a1 * w1.z; acc[1][7] += a1 * w1.w;
    }
    #pragma unroll
    for (int i = 0; i < 2; i++) {
        int m = m0 + ty * 2 + i;
        float4 o0 = {acc[i][0], acc[i][1], acc[i][2], acc[i][3]};
        float4 o1 = {acc[i][4], acc[i][5], acc[i][6], acc[i][7]};
        *(float4*)&out[(size_t)m * 512 + tx * 8]     = o0;
        *(float4*)&out[(size_t)m * 512 + tx * 8 + 4] = o1;
    }
}

// ---------------- launch ------------------------------------------------------
extern "C" void kernel_launch(void* const* d_in, const int* in_sizes, int n_in,
                              void* d_out, int out_size)
{
    const float* sat     = (const float*)d_in[0];
    const float* satpos  = (const float*)d_in[1];
    const float* ts      = (const float*)d_in[2];
    const float* tspos   = (const float*)d_in[3];
    const float* lsg     = (const float*)d_in[4];
    const float* lsb     = (const float*)d_in[5];
    const float* ltg     = (const float*)d_in[6];
    const float* ltb     = (const float*)d_in[7];
    const float* Wv      = (const float*)d_in[8];
    const float* bv      = (const float*)d_in[9];
    const float* Wq      = (const float*)d_in[10];
    const float* bq      = (const float*)d_in[11];
    const float* Wk      = (const float*)d_in[12];
    const float* bk      = (const float*)d_in[13];
    const float* Wsat    = (const float*)d_in[14];
    const float* bsat    = (const float*)d_in[15];
    const float* Wts     = (const float*)d_in[16];
    const float* bts     = (const float*)d_in[17];
    const float* Wh      = (const float*)d_in[18];

    float* out      = (float*)d_out;
    float* attn_out = out + OUT0_ELEMS;

    float *p_satln, *p_tsln, *p_q, *p_k, *p_ss, *p_cs, *p_st, *p_ct, *p_v;
    float *p_WtQ, *p_WtK, *p_WtSat, *p_WtTs, *p_WtV;
    cudaGetSymbolAddress((void**)&p_satln, g_sat_ln);
    cudaGetSymbolAddress((void**)&p_tsln,  g_ts_ln);
    cudaGetSymbolAddress((void**)&p_q,     g_q);
    cudaGetSymbolAddress((void**)&p_k,     g_k);
    cudaGetSymbolAddress((void**)&p_ss,    g_ss);
    cudaGetSymbolAddress((void**)&p_cs,    g_cs);
    cudaGetSymbolAddress((void**)&p_st,    g_st);
    cudaGetSymbolAddress((void**)&p_ct,    g_ct);
    cudaGetSymbolAddress((void**)&p_v,     g_v);
    cudaGetSymbolAddress((void**)&p_WtQ,   g_WtQ);
    cudaGetSymbolAddress((void**)&p_WtK,   g_WtK);
    cudaGetSymbolAddress((void**)&p_WtSat, g_WtSat);
    cudaGetSymbolAddress((void**)&p_WtTs,  g_WtTs);
    cudaGetSymbolAddress((void**)&p_WtV,   g_WtV);

    cudaFuncSetAttribute(attn_kernel, cudaFuncAttributeMaxDynamicSharedMemorySize, ATTN_SMEM);
    cudaFuncSetAttribute(out_kernel,  cudaFuncAttributeMaxDynamicSharedMemorySize, 64 * 512 * 4);
    cudaFuncSetAttribute(gemm_mma,    cudaFuncAttributeMaxDynamicSharedMemorySize, GEMM_SMEM);

    // 1. LayerNorms
    ln_kernel<<<2 * M_ROWS, 128>>>(sat, ts, lsg, lsb, ltg, ltb);

    // 2. transpose weights to K-major (full fp32)
    transpose_w<<<dim3(8, 8), 256>>>(Wq,   p_WtQ);
    transpose_w<<<dim3(8, 8), 256>>>(Wk,   p_WtK);
    transpose_w<<<dim3(8, 8), 256>>>(Wsat, p_WtSat);
    transpose_w<<<dim3(8, 8), 256>>>(Wts,  p_WtTs);
    transpose_w<<<dim3(1, 8), 256>>>(Wv,   p_WtV);

    // 3. 3xTF32 mma.sync projections
    dim3 gg(M_ROWS / 128, 8);
    gemm_mma<<<gg, 256, GEMM_SMEM>>>(p_tsln,             p_WtQ,   bq,   p_q,  0);
    gemm_mma<<<gg, 256, GEMM_SMEM>>>(p_satln,            p_WtK,   bk,   p_k,  0);
    gemm_mma<<<gg, 256, GEMM_SMEM>>>(satpos,             p_WtSat, bsat, p_ss, 0);
    gemm_mma<<<gg, 256, GEMM_SMEM>>>(satpos + TOK_ELEMS, p_WtSat, bsat, p_cs, 0);
    gemm_mma<<<gg, 256, GEMM_SMEM>>>(tspos,              p_WtTs,  bts,  p_st, 0);
    gemm_mma<<<gg, 256, GEMM_SMEM>>>(tspos + TOK_ELEMS,  p_WtTs,  bts,  p_ct, 0);
    gemm_mma<<<dim3(M_ROWS / 128, 1), 256, GEMM_SMEM>>>(p_satln, p_WtV, bv, p_v, 1);

    // 4. RoPE (emits split bf16 q/k)
    rope_kernel<<<PROJ_ELEMS / 256, 256>>>();

    // 5. attention (bf16x3 tensor QK^T + fp32 softmax + FFMA PV)
    dim3 ga(L_ / QT, H_, B_);
    attn_kernel<<<ga, 256, ATTN_SMEM>>>(attn_out);

    // 6. out = mean_h(head) @ Wh
    out_kernel<<<M_ROWS / 8, 256, 64 * 512 * 4>>>(Wh, out);
}

// round 9
// speedup vs baseline: 1.7757x; 1.1999x over previous
#include <cuda_runtime.h>
#include <cuda_bf16.h>
#include <cstdint>

// Problem constants
#define B_   16
#define L_   1024
#define D_   512
#define H_   8
#define DK_  64
#define M_ROWS   (B_ * L_)            // 16384
#define TOK_ELEMS  (B_ * L_ * D_)     // 8388608
#define PROJ_ELEMS (B_ * H_ * L_ * DK_) // 8388608
#define OUT0_ELEMS ((size_t)B_ * L_ * D_)

// ---------------- scratch (device globals) ------------------------------------
__device__ float g_sat_ln[TOK_ELEMS];
__device__ float g_ts_ln[TOK_ELEMS];
__device__ float g_q[PROJ_ELEMS];
__device__ float g_k[PROJ_ELEMS];
__device__ float g_ss[PROJ_ELEMS];
__device__ float g_cs[PROJ_ELEMS];
__device__ float g_st[PROJ_ELEMS];
__device__ float g_ct[PROJ_ELEMS];
__device__ float g_v[B_ * L_ * DK_];
__device__ float g_head[PROJ_ELEMS];
// transposed weights (K-major rows of length 512): (H, DK, D)
__device__ float g_WtQ[H_ * DK_ * D_];
__device__ float g_WtK[H_ * DK_ * D_];
__device__ float g_WtSat[H_ * DK_ * D_];
__device__ float g_WtTs[H_ * DK_ * D_];
__device__ float g_WtV[DK_ * D_];
// post-RoPE q/k as split bf16 (big + small) for tensor-core QK^T
__device__ __nv_bfloat16 g_qb[PROJ_ELEMS];
__device__ __nv_bfloat16 g_qs[PROJ_ELEMS];
__device__ __nv_bfloat16 g_kb[PROJ_ELEMS];
__device__ __nv_bfloat16 g_ks[PROJ_ELEMS];
// V^T packed operands: per (b,d) row of 1024 uint32; Vdup=(vb,vb), Vcmp=(vs,0)
__device__ uint32_t g_vd[B_ * DK_ * L_];
__device__ uint32_t g_vc[B_ * DK_ * L_];

// ---------------- PTX helpers (portable: compute_80+) --------------------------
__device__ __forceinline__ uint32_t smem_u32(const void* p) {
    uint32_t a;
    asm("{ .reg .u64 t; cvta.to.shared.u64 t, %1; cvt.u32.u64 %0, t; }" : "=r"(a) : "l"(p));
    return a;
}
#define CP_ASYNC16(dst, src) \
    asm volatile("cp.async.cg.shared.global [%0], [%1], 16;" :: "r"(dst), "l"(src) : "memory")
#define CP_COMMIT() asm volatile("cp.async.commit_group;" ::: "memory")
#define CP_WAIT0()  asm volatile("cp.async.wait_group 0;" ::: "memory")
#define CP_WAIT1()  asm volatile("cp.async.wait_group 1;" ::: "memory")

#define LDSM_X4(r0, r1, r2, r3, addr) \
    asm volatile("ldmatrix.sync.aligned.m8n8.x4.shared.b16 {%0,%1,%2,%3}, [%4];" \
        : "=r"(r0), "=r"(r1), "=r"(r2), "=r"(r3) : "r"(addr))

#define MMA_TF32(c, a0, a1, a2, a3, b0, b1) \
    asm volatile("mma.sync.aligned.m16n8k8.row.col.f32.tf32.tf32.f32 " \
        "{%0,%1,%2,%3},{%4,%5,%6,%7},{%8,%9},{%0,%1,%2,%3};" \
        : "+f"((c)[0]), "+f"((c)[1]), "+f"((c)[2]), "+f"((c)[3]) \
        : "r"(a0), "r"(a1), "r"(a2), "r"(a3), "r"(b0), "r"(b1))

#define MMA_BF16(c, a0, a1, a2, a3, b0, b1) \
    asm volatile("mma.sync.aligned.m16n8k16.row.col.f32.bf16.bf16.f32 " \
        "{%0,%1,%2,%3},{%4,%5,%6,%7},{%8,%9},{%0,%1,%2,%3};" \
        : "+f"((c)[0]), "+f"((c)[1]), "+f"((c)[2]), "+f"((c)[3]) \
        : "r"(a0), "r"(a1), "r"(a2), "r"(a3), "r"(b0), "r"(b1))

__device__ __forceinline__ void tf32_split(uint32_t x, uint32_t& big, uint32_t& sml) {
    float xf = __uint_as_float(x);
    asm("cvt.rna.tf32.f32 %0, %1;" : "=r"(big) : "f"(xf));
    float r = xf - __uint_as_float(big);
    asm("cvt.rna.tf32.f32 %0, %1;" : "=r"(sml) : "f"(r));
}
__device__ __forceinline__ void bf16_split(float x, __nv_bfloat16& big, __nv_bfloat16& sml) {
    big = __float2bfloat16_rn(x);
    sml = __float2bfloat16_rn(x - __bfloat162float(big));
}
__device__ __forceinline__ uint16_t bf_bits(__nv_bfloat16 v) {
    uint16_t u; *(__nv_bfloat16*)&u = v; return u;
}

// ---------------- LayerNorm ---------------------------------------------------
__global__ void ln_kernel(const float* __restrict__ sat, const float* __restrict__ ts,
                          const float* __restrict__ gs, const float* __restrict__ bs,
                          const float* __restrict__ gt, const float* __restrict__ bt)
{
    int rid = blockIdx.x;
    const float* src; float* dst; const float* g; const float* bb;
    if (rid < M_ROWS) {
        src = sat + (size_t)rid * D_; dst = g_sat_ln + (size_t)rid * D_; g = gs; bb = bs;
    } else {
        int r = rid - M_ROWS;
        src = ts + (size_t)r * D_;   dst = g_ts_ln + (size_t)r * D_;  g = gt; bb = bt;
    }
    int t = threadIdx.x;
    float4 x = ((const float4*)src)[t];
    float s  = x.x + x.y + x.z + x.w;
    float sq = x.x*x.x + x.y*x.y + x.z*x.z + x.w*x.w;
    #pragma unroll
    for (int o = 16; o; o >>= 1) {
        s  += __shfl_xor_sync(0xFFFFFFFFu, s,  o);
        sq += __shfl_xor_sync(0xFFFFFFFFu, sq, o);
    }
    __shared__ float ws[4], wq[4];
    if ((t & 31) == 0) { ws[t >> 5] = s; wq[t >> 5] = sq; }
    __syncthreads();
    s  = ws[0] + ws[1] + ws[2] + ws[3];
    sq = wq[0] + wq[1] + wq[2] + wq[3];
    float m   = s * (1.0f / D_);
    float var = sq * (1.0f / D_) - m * m;
    float inv = rsqrtf(var + 1e-5f);
    float4 g4 = ((const float4*)g)[t];
    float4 b4 = ((const float4*)bb)[t];
    float4 o;
    o.x = (x.x - m) * inv * g4.x + b4.x;
    o.y = (x.y - m) * inv * g4.y + b4.y;
    o.z = (x.z - m) * inv * g4.z + b4.z;
    o.w = (x.w - m) * inv * g4.w + b4.w;
    ((float4*)dst)[t] = o;
}

// ---------------- weight transpose: W (Hn,512,64) -> Wt (Hn,64,512) -----------
__global__ void transpose_w(const float* __restrict__ W, float* __restrict__ Wt)
{
    __shared__ float t[64][65];
    int h = blockIdx.x, k0 = blockIdx.y * 64;
    const float* Wp = W + (size_t)h * (D_ * DK_);
    float* Wo = Wt + (size_t)h * (DK_ * D_);
    #pragma unroll
    for (int i = 0; i < 16; i++) {
        int e = threadIdx.x + i * 256;
        int r = e >> 6, c = e & 63;
        t[r][c] = Wp[(size_t)(k0 + r) * 64 + c];
    }
    __syncthreads();
    #pragma unroll
    for (int i = 0; i < 16; i++) {
        int e = threadIdx.x + i * 256;
        int n = e >> 6, kk = e & 63;
        Wo[(size_t)n * 512 + k0 + kk] = t[kk][n];
    }
}

// ---------------- V prep: build packed V^T operands ----------------------------
// grid (B_, 16); each block: 64 keys x 64 dims tile
__global__ void vprep_kernel()
{
    __shared__ float t[64][65];
    int b = blockIdx.x, k0 = blockIdx.y * 64;
    int tid = threadIdx.x;
    #pragma unroll
    for (int i = 0; i < 16; i++) {
        int e = tid + i * 256;
        int k = e >> 6, d = e & 63;
        t[k][d] = g_v[((size_t)b * L_ + k0 + k) * 64 + d];
    }
    __syncthreads();
    #pragma unroll
    for (int i = 0; i < 16; i++) {
        int e = tid + i * 256;
        int d = e >> 6, k = e & 63;
        __nv_bfloat16 vb, vs;
        bf16_split(t[k][d], vb, vs);
        size_t off = ((size_t)b * DK_ + d) * L_ + k0 + k;
        uint32_t ub = bf_bits(vb), us = bf_bits(vs);
        g_vd[off] = ub | (ub << 16);
        g_vc[off] = us;                      // high half = 0
    }
}

// ---------------- 3xTF32 mma.sync projection GEMM (proven R4) ------------------
#define ASTRIDE 36
#define ASZ (128 * ASTRIDE * 4)
#define BSZ (64  * ASTRIDE * 4)
#define STG (ASZ + BSZ)
#define GEMM_SMEM (2 * STG)              // 55296 B

__global__ void __launch_bounds__(256) gemm_mma(const float* __restrict__ A,
                                                const float* __restrict__ Bt,
                                                const float* __restrict__ bias,
                                                float* __restrict__ C,
                                                int is_v)
{
    extern __shared__ __align__(16) char smraw[];
    uint32_t sb = smem_u32(smraw);
    int tid = threadIdx.x;
    int lane = tid & 31, wid = tid >> 5;
    int warp_m = wid >> 1, warp_n = wid & 1;
    int m0 = blockIdx.x * 128, by = blockIdx.y, n0 = by * 64;

    int t8 = lane & 7, sel = lane >> 3;
    uint32_t aOff = (uint32_t)(((warp_m * 32 + (sel & 1) * 8 + t8) * ASTRIDE + (sel >> 1) * 4) * 4);
    uint32_t bOff = (uint32_t)(((warp_n * 32 + (sel >> 1) * 8 + t8) * ASTRIDE + (sel & 1) * 4) * 4);

    float c[8][4];
    #pragma unroll
    for (int i = 0; i < 8; i++)
        #pragma unroll
        for (int j = 0; j < 4; j++) c[i][j] = 0.0f;

    auto load_stage = [&](int s, int k0) {
        uint32_t ab = sb + s * STG, bbs = ab + ASZ;
        #pragma unroll
        for (int i = 0; i < 4; i++) {
            int e = tid + i * 256, r = e >> 3, c4 = e & 7;
            CP_ASYNC16(ab + (uint32_t)((r * ASTRIDE + c4 * 4) * 4),
                       A + (size_t)(m0 + r) * 512 + k0 + c4 * 4);
        }
        #pragma unroll
        for (int i = 0; i < 2; i++) {
            int e = tid + i * 256, r = e >> 3, c4 = e & 7;
            CP_ASYNC16(bbs + (uint32_t)((r * ASTRIDE + c4 * 4) * 4),
                       Bt + (size_t)(n0 + r) * 512 + k0 + c4 * 4);
        }
    };

    auto compute = [&](int s) {
        uint32_t ab = sb + s * STG + aOff;
        uint32_t bb = sb + s * STG + ASZ + bOff;
        #pragma unroll
        for (int ks = 0; ks < 4; ks++) {
            uint32_t a[8], b[8];
            LDSM_X4(a[0], a[1], a[2], a[3], ab + ks * 32);
            LDSM_X4(a[4], a[5], a[6], a[7], ab + (uint32_t)(16 * ASTRIDE * 4) + ks * 32);
            LDSM_X4(b[0], b[1], b[2], b[3], bb + ks * 32);
            LDSM_X4(b[4], b[5], b[6], b[7], bb + (uint32_t)(16 * ASTRIDE * 4) + ks * 32);
            uint32_t aB[8], aS[8], bB[8], bS[8];
            #pragma unroll
            for (int i = 0; i < 8; i++) { tf32_split(a[i], aB[i], aS[i]); tf32_split(b[i], bB[i], bS[i]); }
            #pragma unroll
            for (int i = 0; i < 2; i++)
                #pragma unroll
                for (int j = 0; j < 4; j++) {
                    float* cc = c[i * 4 + j];
                    MMA_TF32(cc, aS[i*4], aS[i*4+1], aS[i*4+2], aS[i*4+3], bB[j*2], bB[j*2+1]);
                    MMA_TF32(cc, aB[i*4], aB[i*4+1], aB[i*4+2], aB[i*4+3], bS[j*2], bS[j*2+1]);
                    MMA_TF32(cc, aB[i*4], aB[i*4+1], aB[i*4+2], aB[i*4+3], bB[j*2], bB[j*2+1]);
                }
        }
    };

    load_stage(0, 0);
    CP_COMMIT();
    for (int ck = 0; ck < 16; ck++) {
        if (ck < 15) {
            load_stage((ck + 1) & 1, (ck + 1) * 32);
            CP_COMMIT();
            CP_WAIT1();
        } else {
            CP_WAIT0();
        }
        __syncthreads();
        compute(ck & 1);
        __syncthreads();
    }

    int r_lane = lane >> 2, c_lane = (lane & 3) * 2;
    #pragma unroll
    for (int i = 0; i < 2; i++) {
        #pragma unroll
        for (int j = 0; j < 4; j++) {
            float* cc = c[i * 4 + j];
            int nc = warp_n * 32 + j * 8 + c_lane;
            int mrow = m0 + warp_m * 32 + i * 16 + r_lane;
            float2 bb2;
            size_t base0, base1;
            if (is_v) {
                bb2 = *(const float2*)&bias[nc];
                base0 = (size_t)mrow * 64 + nc;
                base1 = (size_t)(mrow + 8) * 64 + nc;
            } else {
                bb2 = *(const float2*)&bias[by * 64 + nc];
                int b0r = mrow >> 10, l0r = mrow & 1023;
                int b1r = (mrow + 8) >> 10, l1r = (mrow + 8) & 1023;
                base0 = ((((size_t)(b0r * 8 + by)) << 10) + l0r) * 64 + nc;
                base1 = ((((size_t)(b1r * 8 + by)) << 10) + l1r) * 64 + nc;
            }
            float2 o0 = {cc[0] + bb2.x, cc[1] + bb2.y};
            float2 o1 = {cc[2] + bb2.x, cc[3] + bb2.y};
            *(float2*)&C[base0] = o0;
            *(float2*)&C[base1] = o1;
        }
    }
}

// ---------------- RoPE (emits split bf16 q/k for tensor QK^T) ------------------
__global__ void rope_kernel()
{
    const int Np = PROJ_ELEMS / 2;
    int idx = blockIdx.x * blockDim.x + threadIdx.x;
    const float2 *xb, *cb, *sb; __nv_bfloat162 *ob, *os;
    if (idx < Np) {
        xb = (const float2*)g_q; cb = (const float2*)g_ct; sb = (const float2*)g_st;
        ob = (__nv_bfloat162*)g_qb; os = (__nv_bfloat162*)g_qs;
    } else {
        idx -= Np;
        xb = (const float2*)g_k; cb = (const float2*)g_cs; sb = (const float2*)g_ss;
        ob = (__nv_bfloat162*)g_kb; os = (__nv_bfloat162*)g_ks;
    }
    float2 x = xb[idx];
    float2 c = cb[idx];
    float2 s = sb[idx];
    float ox = x.x * c.x - x.y * s.x;
    float oy = x.y * c.y + x.x * s.y;
    __nv_bfloat16 b0, s0, b1, s1;
    bf16_split(ox, b0, s0);
    bf16_split(oy, b1, s1);
    __nv_bfloat162 vb; vb.x = b0; vb.y = b1;
    __nv_bfloat162 vs; vs.x = s0; vs.y = s1;
    ob[idx] = vb;
    os[idx] = vs;
}

// ---------------- attention: bf16x3 QK^T + packed-bf16 MMA PV -------------------
#define QT  32
#define KT  256
#define SCP 1028                          // fp32/uint32 row stride (16B-aligned rows)
#define STRK 144                          // bf16 K tile row stride (bytes)
#define STRV 528                          // packed V tile row stride (bytes)
#define SC_BYTES   (QT * SCP * 4)         // 131584
#define KREG_OFF   SC_BYTES
#define KREG_BYTES (2 * KT * STRK)        // 73728 ; V phase uses 2*64*528=67584
#define VC_OFF     (64 * STRV)            // 33792 (Vcmp within kreg)
#define QREG_OFF   (KREG_OFF + KREG_BYTES)
#define QB_BYTES   (QT * STRK)            // 4608
#define ATTN_SMEM  (QREG_OFF + 2 * QB_BYTES)   // 214528

__global__ void __launch_bounds__(256) attn_kernel(float* __restrict__ attn_out)
{
    extern __shared__ __align__(16) float smf[];
    float* sc  = smf;
    uint32_t* scu = (uint32_t*)smf;
    char*  kreg = (char*)smf + KREG_OFF;
    char*  qreg = (char*)smf + QREG_OFF;

    int tid = threadIdx.x, lane = tid & 31, wid = tid >> 5;
    int q0 = blockIdx.x * QT;
    int h  = blockIdx.y;
    int b  = blockIdx.z;
    size_t bh = (size_t)(b * H_ + h);

    uint32_t skb = smem_u32(kreg), sqb = smem_u32(qreg), ssb = smem_u32(sc);

    // load q tile (32 rows x 64 bf16, big + small)
    {
        int r = tid >> 3, cch = tid & 7;
        const uint4* srcb = (const uint4*)&g_qb[((bh << 10) + q0 + r) * 64];
        const uint4* srcs = (const uint4*)&g_qs[((bh << 10) + q0 + r) * 64];
        *(uint4*)(qreg + r * STRK + cch * 16)            = srcb[cch];
        *(uint4*)(qreg + QB_BYTES + r * STRK + cch * 16) = srcs[cch];
    }

    // QK^T fragment lane offsets
    uint32_t aB0 = sqb + (uint32_t)(((lane & 7) + ((lane >> 3) & 1) * 8) * STRK + (lane >> 4) * 16);
    uint32_t aS0 = aB0 + QB_BYTES;
    uint32_t bB0 = skb + (uint32_t)((wid * 32 + (lane & 7) + ((lane >> 3) & 1) * 8) * STRK + (lane >> 4) * 16);
    uint32_t bS0 = bB0 + (uint32_t)(KT * STRK);

    // ---- scores ----
    for (int kt = 0; kt < 4; kt++) {
        __syncthreads();
        size_t kbase = ((bh << 10) + kt * KT) * 64;
        #pragma unroll
        for (int i = 0; i < 8; i++) {
            int e = tid + i * 256, r = e >> 3, cch = e & 7;
            const uint4* srcb = (const uint4*)&g_kb[kbase + (size_t)r * 64];
            const uint4* srcs = (const uint4*)&g_ks[kbase + (size_t)r * 64];
            *(uint4*)(kreg + r * STRK + cch * 16)             = srcb[cch];
            *(uint4*)(kreg + KT * STRK + r * STRK + cch * 16) = srcs[cch];
        }
        __syncthreads();

        float c[2][4][4];
        #pragma unroll
        for (int mt = 0; mt < 2; mt++)
            #pragma unroll
            for (int j = 0; j < 4; j++)
                #pragma unroll
                for (int e = 0; e < 4; e++) c[mt][j][e] = 0.0f;

        #pragma unroll
        for (int ks = 0; ks < 4; ks++) {
            uint32_t aB[2][4], aS[2][4], bB[2][4], bS[2][4];
            #pragma unroll
            for (int mt = 0; mt < 2; mt++) {
                LDSM_X4(aB[mt][0], aB[mt][1], aB[mt][2], aB[mt][3], aB0 + mt * (16 * STRK) + ks * 32);
                LDSM_X4(aS[mt][0], aS[mt][1], aS[mt][2], aS[mt][3], aS0 + mt * (16 * STRK) + ks * 32);
            }
            #pragma unroll
            for (int nt = 0; nt < 2; nt++) {
                LDSM_X4(bB[nt][0], bB[nt][1], bB[nt][2], bB[nt][3], bB0 + nt * (16 * STRK) + ks * 32);
                LDSM_X4(bS[nt][0], bS[nt][1], bS[nt][2], bS[nt][3], bS0 + nt * (16 * STRK) + ks * 32);
            }
            #pragma unroll
            for (int mt = 0; mt < 2; mt++)
                #pragma unroll
                for (int j = 0; j < 4; j++) {
                    int nt = j >> 1, hh = j & 1;
                    float* cc = c[mt][j];
                    MMA_BF16(cc, aS[mt][0], aS[mt][1], aS[mt][2], aS[mt][3], bB[nt][hh], bB[nt][2 + hh]);
                    MMA_BF16(cc, aB[mt][0], aB[mt][1], aB[mt][2], aB[mt][3], bS[nt][hh], bS[nt][2 + hh]);
                    MMA_BF16(cc, aB[mt][0], aB[mt][1], aB[mt][2], aB[mt][3], bB[nt][hh], bB[nt][2 + hh]);
                }
        }
        int rr = lane >> 2, ccl = (lane & 3) * 2;
        #pragma unroll
        for (int mt = 0; mt < 2; mt++)
            #pragma unroll
            for (int j = 0; j < 4; j++) {
                int col = kt * KT + wid * 32 + j * 8 + ccl;
                int row0 = mt * 16 + rr;
                float2 o0 = {c[mt][j][0] * 0.125f, c[mt][j][1] * 0.125f};
                float2 o1 = {c[mt][j][2] * 0.125f, c[mt][j][3] * 0.125f};
                *(float2*)&sc[row0 * SCP + col]       = o0;
                *(float2*)&sc[(row0 + 8) * SCP + col] = o1;
            }
    }
    __syncthreads();

    // ---- softmax: warp wid owns rows wid*4..+3; writes packed (pb|ps<<16) in place
    for (int rr = wid * 4; rr < wid * 4 + 4; rr++) {
        float vals[32];
        float mx = -1e30f;
        #pragma unroll
        for (int j = 0; j < 32; j++) {
            vals[j] = sc[rr * SCP + lane + 32 * j];
            mx = fmaxf(mx, vals[j]);
        }
        #pragma unroll
        for (int o = 16; o; o >>= 1) mx = fmaxf(mx, __shfl_xor_sync(0xFFFFFFFFu, mx, o));
        float s = 0.0f;
        #pragma unroll
        for (int j = 0; j < 32; j++) { vals[j] = __expf(vals[j] - mx); s += vals[j]; }
        #pragma unroll
        for (int o = 16; o; o >>= 1) s += __shfl_xor_sync(0xFFFFFFFFu, s, o);
        float inv = 1.0f / s;
        size_t obase = (((size_t)(b * L_ + q0 + rr) * H_ + h) << 10);
        #pragma unroll
        for (int j = 0; j < 32; j++) {
            float p = vals[j] * inv;
            attn_out[obase + lane + 32 * j] = p;
            __nv_bfloat16 pb, ps;
            bf16_split(p, pb, ps);
            scu[rr * SCP + lane + 32 * j] = (uint32_t)bf_bits(pb) | ((uint32_t)bf_bits(ps) << 16);
        }
    }

    // ---- head = P @ V via packed bf16 MMA (2 MMAs per 8-key step) ----
    int mt = wid >> 2, nt = wid & 3;
    float acc[2][4];
    #pragma unroll
    for (int j = 0; j < 2; j++)
        #pragma unroll
        for (int e = 0; e < 4; e++) acc[j][e] = 0.0f;

    uint32_t aP0 = ssb + (uint32_t)((mt * 16 + (lane & 7) + ((lane >> 3) & 1) * 8) * (SCP * 4) + (lane >> 4) * 16);
    uint32_t vD0 = skb + (uint32_t)((nt * 16 + (lane & 7) + ((lane >> 3) & 1) * 8) * STRV + (lane >> 4) * 16);
    uint32_t vC0 = vD0 + (uint32_t)VC_OFF;

    for (int vt = 0; vt < 8; vt++) {       // 128 keys per chunk
        __syncthreads();
        {
            const uint32_t* vdg = g_vd + ((size_t)b * DK_) * L_ + vt * 128;
            const uint32_t* vcg = g_vc + ((size_t)b * DK_) * L_ + vt * 128;
            #pragma unroll
            for (int i = 0; i < 8; i++) {
                int e = tid + i * 256, r = e >> 5, ch = e & 31;
                *(uint4*)(kreg + r * STRV + ch * 16)          = *(const uint4*)(vdg + (size_t)r * L_ + ch * 4);
                *(uint4*)(kreg + VC_OFF + r * STRV + ch * 16) = *(const uint4*)(vcg + (size_t)r * L_ + ch * 4);
            }
        }
        __syncthreads();
        #pragma unroll
        for (int st = 0; st < 16; st++) {   // 8 real keys per step
            uint32_t a[4], bd[4], bc[4];
            LDSM_X4(a[0], a[1], a[2], a[3], aP0 + (uint32_t)(vt * 512 + st * 32));
            LDSM_X4(bd[0], bd[1], bd[2], bd[3], vD0 + st * 32);
            LDSM_X4(bc[0], bc[1], bc[2], bc[3], vC0 + st * 32);
            #pragma unroll
            for (int j = 0; j < 2; j++) {
                MMA_BF16(acc[j], a[0], a[1], a[2], a[3], bd[j], bd[2 + j]);
                MMA_BF16(acc[j], a[0], a[1], a[2], a[3], bc[j], bc[2 + j]);
            }
        }
    }
    {
        int rr = lane >> 2, cl = (lane & 3) * 2;
        #pragma unroll
        for (int j = 0; j < 2; j++) {
            int col = nt * 16 + j * 8 + cl;
            int row0 = mt * 16 + rr;
            float2 o0 = {acc[j][0], acc[j][1]};
            float2 o1 = {acc[j][2], acc[j][3]};
            *(float2*)&g_head[((bh << 10) + q0 + row0) * 64 + col]     = o0;
            *(float2*)&g_head[((bh << 10) + q0 + row0 + 8) * 64 + col] = o1;
        }
    }
}

// ---------------- final: out = mean_h(head) @ Wh ------------------------------
__global__ void __launch_bounds__(256) out_kernel(const float* __restrict__ Wh,
                                                  float* __restrict__ out)
{
    extern __shared__ __align__(16) float sm2[];
    __shared__ float hm[8][64];
    int tid = threadIdx.x;
    int m0 = blockIdx.x * 8;
    int bb = m0 >> 10;
    int l0 = m0 & 1023;

    #pragma unroll
    for (int i = 0; i < 32; i++) {
        int e = tid + i * 256;
        ((float4*)sm2)[e] = ((const float4*)Wh)[e];
    }
    #pragma unroll
    for (int i = 0; i < 2; i++) {
        int e = tid + i * 256;
        int r = e >> 6, kk = e & 63;
        float s = 0.0f;
        #pragma unroll
        for (int hh = 0; hh < 8; hh++)
            s += g_head[(((size_t)(bb * H_ + hh) << 10) + l0 + r) * 64 + kk];
        hm[r][kk] = s * 0.125f;
    }
    __syncthreads();

    int ty = tid >> 6;
    int tx = tid & 63;
    float acc[2][8];
    #pragma unroll
    for (int i = 0; i < 2; i++)
        #pragma unroll
        for (int j = 0; j < 8; j++) acc[i][j] = 0.0f;
    #pragma unroll 8
    for (int d = 0; d < 64; d++) {
        float a0 = hm[ty * 2][d];
        float a1 = hm[ty * 2 + 1][d];
        float4 w0 = *(float4*)&sm2[d * 512 + tx * 8];
        float4 w1 = *(float4*)&sm2[d * 512 + tx * 8 + 4];
        acc[0][0] += a0 * w0.x; acc[0][1] += a0 * w0.y; acc[0][2] += a0 * w0.z; acc[0][3] += a0 * w0.w;
        acc[0][4] += a0 * w1.x; acc[0][5] += a0 * w1.y; acc[0][6] += a0 * w1.z; acc[0][7] += a0 * w1.w;
        acc[1][0] += a1 * w0.x; acc[1][1] += a1 * w0.y; acc[1][2] += a1 * w0.z; acc[1][3] += a1 * w0.w;
        acc[1][4] += a1 * w1.x; acc[1][5] += a1 * w1.y; acc[1][6] += a1 * w1.z; acc[1][7] += a1 * w1.w;
    }
    #pragma unroll
    for (int i = 0; i < 2; i++) {
        int m = m0 + ty * 2 + i;
        float4 o0 = {acc[i][0], acc[i][1], acc[i][2], acc[i][3]};
        float4 o1 = {acc[i][4], acc[i][5], acc[i][6], acc[i][7]};
        *(float4*)&out[(size_t)m * 512 + tx * 8]     = o0;
        *(float4*)&out[(size_t)m * 512 + tx * 8 + 4] = o1;
    }
}

// ---------------- launch ------------------------------------------------------
extern "C" void kernel_launch(void* const* d_in, const int* in_sizes, int n_in,
                              void* d_out, int out_size)
{
    const float* sat     = (const float*)d_in[0];
    const float* satpos  = (const float*)d_in[1];
    const float* ts      = (const float*)d_in[2];
    const float* tspos   = (const float*)d_in[3];
    const float* lsg     = (const float*)d_in[4];
    const float* lsb     = (const float*)d_in[5];
    const float* ltg     = (const float*)d_in[6];
    const float* ltb     = (const float*)d_in[7];
    const float* Wv      = (const float*)d_in[8];
    const float* bv      = (const float*)d_in[9];
    const float* Wq      = (const float*)d_in[10];
    const float* bq      = (const float*)d_in[11];
    const float* Wk      = (const float*)d_in[12];
    const float* bk      = (const float*)d_in[13];
    const float* Wsat    = (const float*)d_in[14];
    const float* bsat    = (const float*)d_in[15];
    const float* Wts     = (const float*)d_in[16];
    const float* bts     = (const float*)d_in[17];
    const float* Wh      = (const float*)d_in[18];

    float* out      = (float*)d_out;
    float* attn_out = out + OUT0_ELEMS;

    float *p_satln, *p_tsln, *p_q, *p_k, *p_ss, *p_cs, *p_st, *p_ct, *p_v;
    float *p_WtQ, *p_WtK, *p_WtSat, *p_WtTs, *p_WtV;
    cudaGetSymbolAddress((void**)&p_satln, g_sat_ln);
    cudaGetSymbolAddress((void**)&p_tsln,  g_ts_ln);
    cudaGetSymbolAddress((void**)&p_q,     g_q);
    cudaGetSymbolAddress((void**)&p_k,     g_k);
    cudaGetSymbolAddress((void**)&p_ss,    g_ss);
    cudaGetSymbolAddress((void**)&p_cs,    g_cs);
    cudaGetSymbolAddress((void**)&p_st,    g_st);
    cudaGetSymbolAddress((void**)&p_ct,    g_ct);
    cudaGetSymbolAddress((void**)&p_v,     g_v);
    cudaGetSymbolAddress((void**)&p_WtQ,   g_WtQ);
    cudaGetSymbolAddress((void**)&p_WtK,   g_WtK);
    cudaGetSymbolAddress((void**)&p_WtSat, g_WtSat);
    cudaGetSymbolAddress((void**)&p_WtTs,  g_WtTs);
    cudaGetSymbolAddress((void**)&p_WtV,   g_WtV);

    cudaFuncSetAttribute(attn_kernel, cudaFuncAttributeMaxDynamicSharedMemorySize, ATTN_SMEM);
    cudaFuncSetAttribute(out_kernel,  cudaFuncAttributeMaxDynamicSharedMemorySize, 64 * 512 * 4);
    cudaFuncSetAttribute(gemm_mma,    cudaFuncAttributeMaxDynamicSharedMemorySize, GEMM_SMEM);

    // 1. LayerNorms
    ln_kernel<<<2 * M_ROWS, 128>>>(sat, ts, lsg, lsb, ltg, ltb);

    // 2. transpose weights to K-major (full fp32)
    transpose_w<<<dim3(8, 8), 256>>>(Wq,   p_WtQ);
    transpose_w<<<dim3(8, 8), 256>>>(Wk,   p_WtK);
    transpose_w<<<dim3(8, 8), 256>>>(Wsat, p_WtSat);
    transpose_w<<<dim3(8, 8), 256>>>(Wts,  p_WtTs);
    transpose_w<<<dim3(1, 8), 256>>>(Wv,   p_WtV);

    // 3. 3xTF32 mma.sync projections
    dim3 gg(M_ROWS / 128, 8);
    gemm_mma<<<gg, 256, GEMM_SMEM>>>(p_tsln,             p_WtQ,   bq,   p_q,  0);
    gemm_mma<<<gg, 256, GEMM_SMEM>>>(p_satln,            p_WtK,   bk,   p_k,  0);
    gemm_mma<<<gg, 256, GEMM_SMEM>>>(satpos,             p_WtSat, bsat, p_ss, 0);
    gemm_mma<<<gg, 256, GEMM_SMEM>>>(satpos + TOK_ELEMS, p_WtSat, bsat, p_cs, 0);
    gemm_mma<<<gg, 256, GEMM_SMEM>>>(tspos,              p_WtTs,  bts,  p_st, 0);
    gemm_mma<<<gg, 256, GEMM_SMEM>>>(tspos + TOK_ELEMS,  p_WtTs,  bts,  p_ct, 0);
    gemm_mma<<<dim3(M_ROWS / 128, 1), 256, GEMM_SMEM>>>(p_satln, p_WtV, bv, p_v, 1);

    // 4. RoPE (emits split bf16 q/k) + V operand prep
    rope_kernel<<<PROJ_ELEMS / 256, 256>>>();
    vprep_kernel<<<dim3(B_, 16), 256>>>();

    // 5. attention (bf16x3 QK^T + fp32 softmax + packed bf16 MMA PV)
    dim3 ga(L_ / QT, H_, B_);
    attn_kernel<<<ga, 256, ATTN_SMEM>>>(attn_out);

    // 6. out = mean_h(head) @ Wh
    out_kernel<<<M_ROWS / 8, 256, 64 * 512 * 4>>>(Wh, out);
}

// round 10
// speedup vs baseline: 2.1053x; 1.1857x over previous
#include <cuda_runtime.h>
#include <cuda_bf16.h>
#include <cstdint>

// Problem constants
#define B_   16
#define L_   1024
#define D_   512
#define H_   8
#define DK_  64
#define M_ROWS   (B_ * L_)            // 16384
#define TOK_ELEMS  (B_ * L_ * D_)     // 8388608
#define PROJ_ELEMS (B_ * H_ * L_ * DK_) // 8388608
#define OUT0_ELEMS ((size_t)B_ * L_ * D_)

// ---------------- scratch (device globals) ------------------------------------
// split activations (bf16 big/small): 0=sat_ln 1=ts_ln 2=satpos0 3=satpos1 4=tspos0 5=tspos1
__device__ __nv_bfloat16 g_Ab[6][TOK_ELEMS];
__device__ __nv_bfloat16 g_As[6][TOK_ELEMS];
// split transposed weights (K-major rows of 512): 0=Wq 1=Wk 2=Wsat 3=Wts
__device__ __nv_bfloat16 g_Wb[4][H_ * DK_ * D_];
__device__ __nv_bfloat16 g_Ws[4][H_ * DK_ * D_];
__device__ __nv_bfloat16 g_WVb[DK_ * D_];
__device__ __nv_bfloat16 g_WVs[DK_ * D_];

__device__ float g_q[PROJ_ELEMS];
__device__ float g_k[PROJ_ELEMS];
__device__ float g_ss[PROJ_ELEMS];
__device__ float g_cs[PROJ_ELEMS];
__device__ float g_st[PROJ_ELEMS];
__device__ float g_ct[PROJ_ELEMS];
__device__ float g_v[B_ * L_ * DK_];
__device__ float g_head[PROJ_ELEMS];
// post-RoPE q/k as split bf16 (big + small) for tensor-core QK^T
__device__ __nv_bfloat16 g_qb[PROJ_ELEMS];
__device__ __nv_bfloat16 g_qs[PROJ_ELEMS];
__device__ __nv_bfloat16 g_kb[PROJ_ELEMS];
__device__ __nv_bfloat16 g_ks[PROJ_ELEMS];
// V^T packed operands: per (b,d) row of 1024 uint32; Vdup=(vb,vb), Vcmp=(vs,0)
__device__ uint32_t g_vd[B_ * DK_ * L_];
__device__ uint32_t g_vc[B_ * DK_ * L_];

// ---------------- PTX helpers --------------------------------------------------
__device__ __forceinline__ uint32_t smem_u32(const void* p) {
    uint32_t a;
    asm("{ .reg .u64 t; cvta.to.shared.u64 t, %1; cvt.u32.u64 %0, t; }" : "=r"(a) : "l"(p));
    return a;
}
#define CP_ASYNC16(dst, src) \
    asm volatile("cp.async.cg.shared.global [%0], [%1], 16;" :: "r"(dst), "l"(src) : "memory")
#define CP_COMMIT() asm volatile("cp.async.commit_group;" ::: "memory")
#define CP_WAIT0()  asm volatile("cp.async.wait_group 0;" ::: "memory")
#define CP_WAIT1()  asm volatile("cp.async.wait_group 1;" ::: "memory")

#define LDSM_X4(r0, r1, r2, r3, addr) \
    asm volatile("ldmatrix.sync.aligned.m8n8.x4.shared.b16 {%0,%1,%2,%3}, [%4];" \
        : "=r"(r0), "=r"(r1), "=r"(r2), "=r"(r3) : "r"(addr))

#define MMA_BF16(c, a0, a1, a2, a3, b0, b1) \
    asm volatile("mma.sync.aligned.m16n8k16.row.col.f32.bf16.bf16.f32 " \
        "{%0,%1,%2,%3},{%4,%5,%6,%7},{%8,%9},{%0,%1,%2,%3};" \
        : "+f"((c)[0]), "+f"((c)[1]), "+f"((c)[2]), "+f"((c)[3]) \
        : "r"(a0), "r"(a1), "r"(a2), "r"(a3), "r"(b0), "r"(b1))

__device__ __forceinline__ void bf16_split(float x, __nv_bfloat16& big, __nv_bfloat16& sml) {
    big = __float2bfloat16_rn(x);
    sml = __float2bfloat16_rn(x - __bfloat162float(big));
}
__device__ __forceinline__ uint16_t bf_bits(__nv_bfloat16 v) {
    uint16_t u; *(__nv_bfloat16*)&u = v; return u;
}

// ---------------- LayerNorm (emits split bf16) ---------------------------------
__global__ void ln_kernel(const float* __restrict__ sat, const float* __restrict__ ts,
                          const float* __restrict__ gs, const float* __restrict__ bs,
                          const float* __restrict__ gt, const float* __restrict__ bt)
{
    int rid = blockIdx.x;
    const float* src; __nv_bfloat16 *db, *ds; const float* g; const float* bb;
    if (rid < M_ROWS) {
        src = sat + (size_t)rid * D_;
        db = g_Ab[0] + (size_t)rid * D_;  ds = g_As[0] + (size_t)rid * D_;
        g = gs; bb = bs;
    } else {
        int r = rid - M_ROWS;
        src = ts + (size_t)r * D_;
        db = g_Ab[1] + (size_t)r * D_;    ds = g_As[1] + (size_t)r * D_;
        g = gt; bb = bt;
    }
    int t = threadIdx.x;
    float4 x = ((const float4*)src)[t];
    float s  = x.x + x.y + x.z + x.w;
    float sq = x.x*x.x + x.y*x.y + x.z*x.z + x.w*x.w;
    #pragma unroll
    for (int o = 16; o; o >>= 1) {
        s  += __shfl_xor_sync(0xFFFFFFFFu, s,  o);
        sq += __shfl_xor_sync(0xFFFFFFFFu, sq, o);
    }
    __shared__ float ws[4], wq[4];
    if ((t & 31) == 0) { ws[t >> 5] = s; wq[t >> 5] = sq; }
    __syncthreads();
    s  = ws[0] + ws[1] + ws[2] + ws[3];
    sq = wq[0] + wq[1] + wq[2] + wq[3];
    float m   = s * (1.0f / D_);
    float var = sq * (1.0f / D_) - m * m;
    float inv = rsqrtf(var + 1e-5f);
    float4 g4 = ((const float4*)g)[t];
    float4 b4 = ((const float4*)bb)[t];
    float o[4];
    o[0] = (x.x - m) * inv * g4.x + b4.x;
    o[1] = (x.y - m) * inv * g4.y + b4.y;
    o[2] = (x.z - m) * inv * g4.z + b4.z;
    o[3] = (x.w - m) * inv * g4.w + b4.w;
    __nv_bfloat16 big[4], sml[4];
    #pragma unroll
    for (int i = 0; i < 4; i++) bf16_split(o[i], big[i], sml[i]);
    *(uint2*)&db[t * 4] = *(uint2*)big;
    *(uint2*)&ds[t * 4] = *(uint2*)sml;
}

// ---------------- elementwise split (pos embeddings) ---------------------------
__global__ void split_kernel(const float* __restrict__ x, __nv_bfloat16* __restrict__ big,
                             __nv_bfloat16* __restrict__ sml)
{
    int i = blockIdx.x * blockDim.x + threadIdx.x;
    float4 v = ((const float4*)x)[i];
    __nv_bfloat16 b[4], s[4];
    bf16_split(v.x, b[0], s[0]);
    bf16_split(v.y, b[1], s[1]);
    bf16_split(v.z, b[2], s[2]);
    bf16_split(v.w, b[3], s[3]);
    *(uint2*)&big[(size_t)i * 4] = *(uint2*)b;
    *(uint2*)&sml[(size_t)i * 4] = *(uint2*)s;
}

// ---------------- weight transpose + split: (Hn,512,64) -> (Hn,64,512) ---------
__global__ void transpose_w(const float* __restrict__ W,
                            __nv_bfloat16* __restrict__ Wb, __nv_bfloat16* __restrict__ Wsml)
{
    __shared__ float t[64][65];
    int h = blockIdx.x, k0 = blockIdx.y * 64;
    const float* Wp = W + (size_t)h * (D_ * DK_);
    #pragma unroll
    for (int i = 0; i < 16; i++) {
        int e = threadIdx.x + i * 256;
        int r = e >> 6, c = e & 63;
        t[r][c] = Wp[(size_t)(k0 + r) * 64 + c];
    }
    __syncthreads();
    #pragma unroll
    for (int i = 0; i < 16; i++) {
        int e = threadIdx.x + i * 256;
        int n = e >> 6, kk = e & 63;
        __nv_bfloat16 big, sml;
        bf16_split(t[kk][n], big, sml);
        size_t off = (size_t)h * (DK_ * D_) + (size_t)n * 512 + k0 + kk;
        Wb[off] = big;
        Wsml[off] = sml;
    }
}

// ---------------- V prep: build packed V^T operands ----------------------------
__global__ void vprep_kernel()
{
    __shared__ float t[64][65];
    int b = blockIdx.x, k0 = blockIdx.y * 64;
    int tid = threadIdx.x;
    #pragma unroll
    for (int i = 0; i < 16; i++) {
        int e = tid + i * 256;
        int k = e >> 6, d = e & 63;
        t[k][d] = g_v[((size_t)b * L_ + k0 + k) * 64 + d];
    }
    __syncthreads();
    #pragma unroll
    for (int i = 0; i < 16; i++) {
        int e = tid + i * 256;
        int d = e >> 6, k = e & 63;
        __nv_bfloat16 vb, vs;
        bf16_split(t[k][d], vb, vs);
        size_t off = ((size_t)b * DK_ + d) * L_ + k0 + k;
        uint32_t ub = bf_bits(vb), us = bf_bits(vs);
        g_vd[off] = ub | (ub << 16);
        g_vc[off] = us;
    }
}

// ---------------- 3xBF16 projection GEMM (stride-144 packed rows) ---------------
// Row layout: [32 bf16 big | 32 bf16 small] = 128 B data + 16 B pad -> conflict-free
#define GSTR 144
#define GA_SZ (128 * GSTR)               // 18432
#define GB_SZ (64 * GSTR)                // 9216
#define GSTG (GA_SZ + GB_SZ)             // 27648
#define GEMM_SMEM (2 * GSTG)             // 55296

__global__ void __launch_bounds__(256) gemm_bf16(const __nv_bfloat16* __restrict__ Ab,
                                                 const __nv_bfloat16* __restrict__ As,
                                                 const __nv_bfloat16* __restrict__ Bb,
                                                 const __nv_bfloat16* __restrict__ Bs,
                                                 const float* __restrict__ bias,
                                                 float* __restrict__ C, int is_v)
{
    extern __shared__ __align__(16) char smraw[];
    uint32_t sb = smem_u32(smraw);
    int tid = threadIdx.x, lane = tid & 31, wid = tid >> 5;
    int warp_m = wid >> 1, warp_n = wid & 1;
    int m0 = blockIdx.x * 128, by = blockIdx.y, n0 = by * 64;

    uint32_t laneA = (uint32_t)((warp_m * 32 + (lane & 7) + ((lane >> 3) & 1) * 8) * GSTR + (lane >> 4) * 16);
    uint32_t laneB = (uint32_t)((warp_n * 32 + (lane & 7) + ((lane >> 3) & 1) * 8) * GSTR + (lane >> 4) * 16);

    float c[8][4];
    #pragma unroll
    for (int i = 0; i < 8; i++)
        #pragma unroll
        for (int j = 0; j < 4; j++) c[i][j] = 0.0f;

    auto load_stage = [&](int s, int k0) {
        uint32_t base = sb + s * GSTG;
        // A: 128 rows x 8 chunks (c<4: big, c>=4: small)
        #pragma unroll
        for (int i = 0; i < 4; i++) {
            int e = tid + i * 256, r = e >> 3, cc = e & 7;
            const __nv_bfloat16* src = (cc < 4)
                ? Ab + (size_t)(m0 + r) * 512 + k0 + cc * 8
                : As + (size_t)(m0 + r) * 512 + k0 + (cc - 4) * 8;
            CP_ASYNC16(base + (uint32_t)(r * GSTR + cc * 16), src);
        }
        // B: 64 rows x 8 chunks
        #pragma unroll
        for (int i = 0; i < 2; i++) {
            int e = tid + i * 256, r = e >> 3, cc = e & 7;
            const __nv_bfloat16* src = (cc < 4)
                ? Bb + (size_t)(n0 + r) * 512 + k0 + cc * 8
                : Bs + (size_t)(n0 + r) * 512 + k0 + (cc - 4) * 8;
            CP_ASYNC16(base + GA_SZ + (uint32_t)(r * GSTR + cc * 16), src);
        }
    };

    auto compute = [&](int s) {
        uint32_t abase = sb + s * GSTG + laneA;
        uint32_t bbase = sb + s * GSTG + GA_SZ + laneB;
        #pragma unroll
        for (int ks = 0; ks < 2; ks++) {
            uint32_t aB[2][4], aS[2][4], bB[2][4], bS[2][4];
            #pragma unroll
            for (int mt = 0; mt < 2; mt++) {
                LDSM_X4(aB[mt][0], aB[mt][1], aB[mt][2], aB[mt][3], abase + mt * (16 * GSTR) + ks * 32);
                LDSM_X4(aS[mt][0], aS[mt][1], aS[mt][2], aS[mt][3], abase + mt * (16 * GSTR) + 64 + ks * 32);
            }
            #pragma unroll
            for (int nt = 0; nt < 2; nt++) {
                LDSM_X4(bB[nt][0], bB[nt][1], bB[nt][2], bB[nt][3], bbase + nt * (16 * GSTR) + ks * 32);
                LDSM_X4(bS[nt][0], bS[nt][1], bS[nt][2], bS[nt][3], bbase + nt * (16 * GSTR) + 64 + ks * 32);
            }
            #pragma unroll
            for (int mt = 0; mt < 2; mt++)
                #pragma unroll
                for (int j = 0; j < 4; j++) {
                    int nt = j >> 1, hh = j & 1;
                    float* cc = c[mt * 4 + j];
                    MMA_BF16(cc, aS[mt][0], aS[mt][1], aS[mt][2], aS[mt][3], bB[nt][hh], bB[nt][2 + hh]);
                    MMA_BF16(cc, aB[mt][0], aB[mt][1], aB[mt][2], aB[mt][3], bS[nt][hh], bS[nt][2 + hh]);
                    MMA_BF16(cc, aB[mt][0], aB[mt][1], aB[mt][2], aB[mt][3], bB[nt][hh], bB[nt][2 + hh]);
                }
        }
    };

    load_stage(0, 0);
    CP_COMMIT();
    for (int ck = 0; ck < 16; ck++) {
        if (ck < 15) {
            load_stage((ck + 1) & 1, (ck + 1) * 32);
            CP_COMMIT();
            CP_WAIT1();
        } else {
            CP_WAIT0();
        }
        __syncthreads();
        compute(ck & 1);
        __syncthreads();
    }

    int r_lane = lane >> 2, c_lane = (lane & 3) * 2;
    #pragma unroll
    for (int i = 0; i < 2; i++) {
        #pragma unroll
        for (int j = 0; j < 4; j++) {
            float* cc = c[i * 4 + j];
            int nc = warp_n * 32 + j * 8 + c_lane;
            int mrow = m0 + warp_m * 32 + i * 16 + r_lane;
            float2 bb2;
            size_t base0, base1;
            if (is_v) {
                bb2 = *(const float2*)&bias[nc];
                base0 = (size_t)mrow * 64 + nc;
                base1 = (size_t)(mrow + 8) * 64 + nc;
            } else {
                bb2 = *(const float2*)&bias[by * 64 + nc];
                int b0r = mrow >> 10, l0r = mrow & 1023;
                int b1r = (mrow + 8) >> 10, l1r = (mrow + 8) & 1023;
                base0 = ((((size_t)(b0r * 8 + by)) << 10) + l0r) * 64 + nc;
                base1 = ((((size_t)(b1r * 8 + by)) << 10) + l1r) * 64 + nc;
            }
            float2 o0 = {cc[0] + bb2.x, cc[1] + bb2.y};
            float2 o1 = {cc[2] + bb2.x, cc[3] + bb2.y};
            *(float2*)&C[base0] = o0;
            *(float2*)&C[base1] = o1;
        }
    }
}

// ---------------- RoPE (emits split bf16 q/k for tensor QK^T) ------------------
__global__ void rope_kernel()
{
    const int Np = PROJ_ELEMS / 2;
    int idx = blockIdx.x * blockDim.x + threadIdx.x;
    const float2 *xb, *cb, *sb; __nv_bfloat162 *ob, *os;
    if (idx < Np) {
        xb = (const float2*)g_q; cb = (const float2*)g_ct; sb = (const float2*)g_st;
        ob = (__nv_bfloat162*)g_qb; os = (__nv_bfloat162*)g_qs;
    } else {
        idx -= Np;
        xb = (const float2*)g_k; cb = (const float2*)g_cs; sb = (const float2*)g_ss;
        ob = (__nv_bfloat162*)g_kb; os = (__nv_bfloat162*)g_ks;
    }
    float2 x = xb[idx];
    float2 c = cb[idx];
    float2 s = sb[idx];
    float ox = x.x * c.x - x.y * s.x;
    float oy = x.y * c.y + x.x * s.y;
    __nv_bfloat16 b0, s0, b1, s1;
    bf16_split(ox, b0, s0);
    bf16_split(oy, b1, s1);
    __nv_bfloat162 vb; vb.x = b0; vb.y = b1;
    __nv_bfloat162 vs; vs.x = s0; vs.y = s1;
    ob[idx] = vb;
    os[idx] = vs;
}

// ---------------- attention: bf16x3 QK^T + packed-bf16 MMA PV (R9, proven) ------
#define QT  32
#define KT  256
#define SCP 1028
#define STRK 144
#define STRV 528
#define SC_BYTES   (QT * SCP * 4)
#define KREG_OFF   SC_BYTES
#define KREG_BYTES (2 * KT * STRK)
#define VC_OFF     (64 * STRV)
#define QREG_OFF   (KREG_OFF + KREG_BYTES)
#define QB_BYTES   (QT * STRK)
#define ATTN_SMEM  (QREG_OFF + 2 * QB_BYTES)

__global__ void __launch_bounds__(256) attn_kernel(float* __restrict__ attn_out)
{
    extern __shared__ __align__(16) float smf[];
    float* sc  = smf;
    uint32_t* scu = (uint32_t*)smf;
    char*  kreg = (char*)smf + KREG_OFF;
    char*  qreg = (char*)smf + QREG_OFF;

    int tid = threadIdx.x, lane = tid & 31, wid = tid >> 5;
    int q0 = blockIdx.x * QT;
    int h  = blockIdx.y;
    int b  = blockIdx.z;
    size_t bh = (size_t)(b * H_ + h);

    uint32_t skb = smem_u32(kreg), sqb = smem_u32(qreg), ssb = smem_u32(sc);

    {
        int r = tid >> 3, cch = tid & 7;
        const uint4* srcb = (const uint4*)&g_qb[((bh << 10) + q0 + r) * 64];
        const uint4* srcs = (const uint4*)&g_qs[((bh << 10) + q0 + r) * 64];
        *(uint4*)(qreg + r * STRK + cch * 16)            = srcb[cch];
        *(uint4*)(qreg + QB_BYTES + r * STRK + cch * 16) = srcs[cch];
    }

    uint32_t aB0 = sqb + (uint32_t)(((lane & 7) + ((lane >> 3) & 1) * 8) * STRK + (lane >> 4) * 16);
    uint32_t aS0 = aB0 + QB_BYTES;
    uint32_t bB0 = skb + (uint32_t)((wid * 32 + (lane & 7) + ((lane >> 3) & 1) * 8) * STRK + (lane >> 4) * 16);
    uint32_t bS0 = bB0 + (uint32_t)(KT * STRK);

    for (int kt = 0; kt < 4; kt++) {
        __syncthreads();
        size_t kbase = ((bh << 10) + kt * KT) * 64;
        #pragma unroll
        for (int i = 0; i < 8; i++) {
            int e = tid + i * 256, r = e >> 3, cch = e & 7;
            const uint4* srcb = (const uint4*)&g_kb[kbase + (size_t)r * 64];
            const uint4* srcs = (const uint4*)&g_ks[kbase + (size_t)r * 64];
            *(uint4*)(kreg + r * STRK + cch * 16)             = srcb[cch];
            *(uint4*)(kreg + KT * STRK + r * STRK + cch * 16) = srcs[cch];
        }
        __syncthreads();

        float c[2][4][4];
        #pragma unroll
        for (int mt = 0; mt < 2; mt++)
            #pragma unroll
            for (int j = 0; j < 4; j++)
                #pragma unroll
                for (int e = 0; e < 4; e++) c[mt][j][e] = 0.0f;

        #pragma unroll
        for (int ks = 0; ks < 4; ks++) {
            uint32_t aB[2][4], aS[2][4], bB[2][4], bS[2][4];
            #pragma unroll
            for (int mt = 0; mt < 2; mt++) {
                LDSM_X4(aB[mt][0], aB[mt][1], aB[mt][2], aB[mt][3], aB0 + mt * (16 * STRK) + ks * 32);
                LDSM_X4(aS[mt][0], aS[mt][1], aS[mt][2], aS[mt][3], aS0 + mt * (16 * STRK) + ks * 32);
            }
            #pragma unroll
            for (int nt = 0; nt < 2; nt++) {
                LDSM_X4(bB[nt][0], bB[nt][1], bB[nt][2], bB[nt][3], bB0 + nt * (16 * STRK) + ks * 32);
                LDSM_X4(bS[nt][0], bS[nt][1], bS[nt][2], bS[nt][3], bS0 + nt * (16 * STRK) + ks * 32);
            }
            #pragma unroll
            for (int mt = 0; mt < 2; mt++)
                #pragma unroll
                for (int j = 0; j < 4; j++) {
                    int nt = j >> 1, hh = j & 1;
                    float* cc = c[mt][j];
                    MMA_BF16(cc, aS[mt][0], aS[mt][1], aS[mt][2], aS[mt][3], bB[nt][hh], bB[nt][2 + hh]);
                    MMA_BF16(cc, aB[mt][0], aB[mt][1], aB[mt][2], aB[mt][3], bS[nt][hh], bS[nt][2 + hh]);
                    MMA_BF16(cc, aB[mt][0], aB[mt][1], aB[mt][2], aB[mt][3], bB[nt][hh], bB[nt][2 + hh]);
                }
        }
        int rr = lane >> 2, ccl = (lane & 3) * 2;
        #pragma unroll
        for (int mt = 0; mt < 2; mt++)
            #pragma unroll
            for (int j = 0; j < 4; j++) {
                int col = kt * KT + wid * 32 + j * 8 + ccl;
                int row0 = mt * 16 + rr;
                float2 o0 = {c[mt][j][0] * 0.125f, c[mt][j][1] * 0.125f};
                float2 o1 = {c[mt][j][2] * 0.125f, c[mt][j][3] * 0.125f};
                *(float2*)&sc[row0 * SCP + col]       = o0;
                *(float2*)&sc[(row0 + 8) * SCP + col] = o1;
            }
    }
    __syncthreads();

    for (int rr = wid * 4; rr < wid * 4 + 4; rr++) {
        float vals[32];
        float mx = -1e30f;
        #pragma unroll
        for (int j = 0; j < 32; j++) {
            vals[j] = sc[rr * SCP + lane + 32 * j];
            mx = fmaxf(mx, vals[j]);
        }
        #pragma unroll
        for (int o = 16; o; o >>= 1) mx = fmaxf(mx, __shfl_xor_sync(0xFFFFFFFFu, mx, o));
        float s = 0.0f;
        #pragma unroll
        for (int j = 0; j < 32; j++) { vals[j] = __expf(vals[j] - mx); s += vals[j]; }
        #pragma unroll
        for (int o = 16; o; o >>= 1) s += __shfl_xor_sync(0xFFFFFFFFu, s, o);
        float inv = 1.0f / s;
        size_t obase = (((size_t)(b * L_ + q0 + rr) * H_ + h) << 10);
        #pragma unroll
        for (int j = 0; j < 32; j++) {
            float p = vals[j] * inv;
            attn_out[obase + lane + 32 * j] = p;
            __nv_bfloat16 pb, ps;
            bf16_split(p, pb, ps);
            scu[rr * SCP + lane + 32 * j] = (uint32_t)bf_bits(pb) | ((uint32_t)bf_bits(ps) << 16);
        }
    }

    int mt = wid >> 2, nt = wid & 3;
    float acc[2][4];
    #pragma unroll
    for (int j = 0; j < 2; j++)
        #pragma unroll
        for (int e = 0; e < 4; e++) acc[j][e] = 0.0f;

    uint32_t aP0 = ssb + (uint32_t)((mt * 16 + (lane & 7) + ((lane >> 3) & 1) * 8) * (SCP * 4) + (lane >> 4) * 16);
    uint32_t vD0 = skb + (uint32_t)((nt * 16 + (lane & 7) + ((lane >> 3) & 1) * 8) * STRV + (lane >> 4) * 16);
    uint32_t vC0 = vD0 + (uint32_t)VC_OFF;

    for (int vt = 0; vt < 8; vt++) {
        __syncthreads();
        {
            const uint32_t* vdg = g_vd + ((size_t)b * DK_) * L_ + vt * 128;
            const uint32_t* vcg = g_vc + ((size_t)b * DK_) * L_ + vt * 128;
            #pragma unroll
            for (int i = 0; i < 8; i++) {
                int e = tid + i * 256, r = e >> 5, ch = e & 31;
                *(uint4*)(kreg + r * STRV + ch * 16)          = *(const uint4*)(vdg + (size_t)r * L_ + ch * 4);
                *(uint4*)(kreg + VC_OFF + r * STRV + ch * 16) = *(const uint4*)(vcg + (size_t)r * L_ + ch * 4);
            }
        }
        __syncthreads();
        #pragma unroll
        for (int st = 0; st < 16; st++) {
            uint32_t a[4], bd[4], bc[4];
            LDSM_X4(a[0], a[1], a[2], a[3], aP0 + (uint32_t)(vt * 512 + st * 32));
            LDSM_X4(bd[0], bd[1], bd[2], bd[3], vD0 + st * 32);
            LDSM_X4(bc[0], bc[1], bc[2], bc[3], vC0 + st * 32);
            #pragma unroll
            for (int j = 0; j < 2; j++) {
                MMA_BF16(acc[j], a[0], a[1], a[2], a[3], bd[j], bd[2 + j]);
                MMA_BF16(acc[j], a[0], a[1], a[2], a[3], bc[j], bc[2 + j]);
            }
        }
    }
    {
        int rr = lane >> 2, cl = (lane & 3) * 2;
        #pragma unroll
        for (int j = 0; j < 2; j++) {
            int col = nt * 16 + j * 8 + cl;
            int row0 = mt * 16 + rr;
            float2 o0 = {acc[j][0], acc[j][1]};
            float2 o1 = {acc[j][2], acc[j][3]};
            *(float2*)&g_head[((bh << 10) + q0 + row0) * 64 + col]     = o0;
            *(float2*)&g_head[((bh << 10) + q0 + row0 + 8) * 64 + col] = o1;
        }
    }
}

// ---------------- final: out = mean_h(head) @ Wh ------------------------------
__global__ void __launch_bounds__(256) out_kernel(const float* __restrict__ Wh,
                                                  float* __restrict__ out)
{
    extern __shared__ __align__(16) float sm2[];
    __shared__ float hm[8][64];
    int tid = threadIdx.x;
    int m0 = blockIdx.x * 8;
    int bb = m0 >> 10;
    int l0 = m0 & 1023;

    #pragma unroll
    for (int i = 0; i < 32; i++) {
        int e = tid + i * 256;
        ((float4*)sm2)[e] = ((const float4*)Wh)[e];
    }
    #pragma unroll
    for (int i = 0; i < 2; i++) {
        int e = tid + i * 256;
        int r = e >> 6, kk = e & 63;
        float s = 0.0f;
        #pragma unroll
        for (int hh = 0; hh < 8; hh++)
            s += g_head[(((size_t)(bb * H_ + hh) << 10) + l0 + r) * 64 + kk];
        hm[r][kk] = s * 0.125f;
    }
    __syncthreads();

    int ty = tid >> 6;
    int tx = tid & 63;
    float acc[2][8];
    #pragma unroll
    for (int i = 0; i < 2; i++)
        #pragma unroll
        for (int j = 0; j < 8; j++) acc[i][j] = 0.0f;
    #pragma unroll 8
    for (int d = 0; d < 64; d++) {
        float a0 = hm[ty * 2][d];
        float a1 = hm[ty * 2 + 1][d];
        float4 w0 = *(float4*)&sm2[d * 512 + tx * 8];
        float4 w1 = *(float4*)&sm2[d * 512 + tx * 8 + 4];
        acc[0][0] += a0 * w0.x; acc[0][1] += a0 * w0.y; acc[0][2] += a0 * w0.z; acc[0][3] += a0 * w0.w;
        acc[0][4] += a0 * w1.x; acc[0][5] += a0 * w1.y; acc[0][6] += a0 * w1.z; acc[0][7] += a0 * w1.w;
        acc[1][0] += a1 * w0.x; acc[1][1] += a1 * w0.y; acc[1][2] += a1 * w0.z; acc[1][3] += a1 * w0.w;
        acc[1][4] += a1 * w1.x; acc[1][5] += a1 * w1.y; acc[1][6] += a1 * w1.z; acc[1][7] += a1 * w1.w;
    }
    #pragma unroll
    for (int i = 0; i < 2; i++) {
        int m = m0 + ty * 2 + i;
        float4 o0 = {acc[i][0], acc[i][1], acc[i][2], acc[i][3]};
        float4 o1 = {acc[i][4], acc[i][5], acc[i][6], acc[i][7]};
        *(float4*)&out[(size_t)m * 512 + tx * 8]     = o0;
        *(float4*)&out[(size_t)m * 512 + tx * 8 + 4] = o1;
    }
}

// ---------------- launch ------------------------------------------------------
extern "C" void kernel_launch(void* const* d_in, const int* in_sizes, int n_in,
                              void* d_out, int out_size)
{
    const float* sat     = (const float*)d_in[0];
    const float* satpos  = (const float*)d_in[1];
    const float* ts      = (const float*)d_in[2];
    const float* tspos   = (const float*)d_in[3];
    const float* lsg     = (const float*)d_in[4];
    const float* lsb     = (const float*)d_in[5];
    const float* ltg     = (const float*)d_in[6];
    const float* ltb     = (const float*)d_in[7];
    const float* Wv      = (const float*)d_in[8];
    const float* bv      = (const float*)d_in[9];
    const float* Wq      = (const float*)d_in[10];
    const float* bq      = (const float*)d_in[11];
    const float* Wk      = (const float*)d_in[12];
    const float* bk      = (const float*)d_in[13];
    const float* Wsat    = (const float*)d_in[14];
    const float* bsat    = (const float*)d_in[15];
    const float* Wts     = (const float*)d_in[16];
    const float* bts     = (const float*)d_in[17];
    const float* Wh      = (const float*)d_in[18];

    float* out      = (float*)d_out;
    float* attn_out = out + OUT0_ELEMS;

    float *p_q, *p_k, *p_ss, *p_cs, *p_st, *p_ct, *p_v;
    __nv_bfloat16 *p_Ab, *p_As, *p_Wb, *p_Ws, *p_WVb, *p_WVs;
    cudaGetSymbolAddress((void**)&p_q,   g_q);
    cudaGetSymbolAddress((void**)&p_k,   g_k);
    cudaGetSymbolAddress((void**)&p_ss,  g_ss);
    cudaGetSymbolAddress((void**)&p_cs,  g_cs);
    cudaGetSymbolAddress((void**)&p_st,  g_st);
    cudaGetSymbolAddress((void**)&p_ct,  g_ct);
    cudaGetSymbolAddress((void**)&p_v,   g_v);
    cudaGetSymbolAddress((void**)&p_Ab,  g_Ab);
    cudaGetSymbolAddress((void**)&p_As,  g_As);
    cudaGetSymbolAddress((void**)&p_Wb,  g_Wb);
    cudaGetSymbolAddress((void**)&p_Ws,  g_Ws);
    cudaGetSymbolAddress((void**)&p_WVb, g_WVb);
    cudaGetSymbolAddress((void**)&p_WVs, g_WVs);

    cudaFuncSetAttribute(attn_kernel, cudaFuncAttributeMaxDynamicSharedMemorySize, ATTN_SMEM);
    cudaFuncSetAttribute(out_kernel,  cudaFuncAttributeMaxDynamicSharedMemorySize, 64 * 512 * 4);
    cudaFuncSetAttribute(gemm_bf16,   cudaFuncAttributeMaxDynamicSharedMemorySize, GEMM_SMEM);

    const size_t WSZ = (size_t)H_ * DK_ * D_;
    const size_t TE  = (size_t)TOK_ELEMS;

    // 1. LayerNorms (emit split bf16)
    ln_kernel<<<2 * M_ROWS, 128>>>(sat, ts, lsg, lsb, ltg, ltb);

    // 2. split pos embeddings
    split_kernel<<<TOK_ELEMS / 1024, 256>>>(satpos,             p_Ab + 2 * TE, p_As + 2 * TE);
    split_kernel<<<TOK_ELEMS / 1024, 256>>>(satpos + TOK_ELEMS, p_Ab + 3 * TE, p_As + 3 * TE);
    split_kernel<<<TOK_ELEMS / 1024, 256>>>(tspos,              p_Ab + 4 * TE, p_As + 4 * TE);
    split_kernel<<<TOK_ELEMS / 1024, 256>>>(tspos + TOK_ELEMS,  p_Ab + 5 * TE, p_As + 5 * TE);

    // 3. transpose + split weights
    transpose_w<<<dim3(8, 8), 256>>>(Wq,   p_Wb + 0 * WSZ, p_Ws + 0 * WSZ);
    transpose_w<<<dim3(8, 8), 256>>>(Wk,   p_Wb + 1 * WSZ, p_Ws + 1 * WSZ);
    transpose_w<<<dim3(8, 8), 256>>>(Wsat, p_Wb + 2 * WSZ, p_Ws + 2 * WSZ);
    transpose_w<<<dim3(8, 8), 256>>>(Wts,  p_Wb + 3 * WSZ, p_Ws + 3 * WSZ);
    transpose_w<<<dim3(1, 8), 256>>>(Wv,   p_WVb, p_WVs);

    // 4. 3xBF16 projections (conflict-free stride-144 layout)
    dim3 gg(M_ROWS / 128, 8);
    gemm_bf16<<<gg, 256, GEMM_SMEM>>>(p_Ab + 1 * TE, p_As + 1 * TE, p_Wb + 0 * WSZ, p_Ws + 0 * WSZ, bq,   p_q,  0);
    gemm_bf16<<<gg, 256, GEMM_SMEM>>>(p_Ab + 0 * TE, p_As + 0 * TE, p_Wb + 1 * WSZ, p_Ws + 1 * WSZ, bk,   p_k,  0);
    gemm_bf16<<<gg, 256, GEMM_SMEM>>>(p_Ab + 2 * TE, p_As + 2 * TE, p_Wb + 2 * WSZ, p_Ws + 2 * WSZ, bsat, p_ss, 0);
    gemm_bf16<<<gg, 256, GEMM_SMEM>>>(p_Ab + 3 * TE, p_As + 3 * TE, p_Wb + 2 * WSZ, p_Ws + 2 * WSZ, bsat, p_cs, 0);
    gemm_bf16<<<gg, 256, GEMM_SMEM>>>(p_Ab + 4 * TE, p_As + 4 * TE, p_Wb + 3 * WSZ, p_Ws + 3 * WSZ, bts,  p_st, 0);
    gemm_bf16<<<gg, 256, GEMM_SMEM>>>(p_Ab + 5 * TE, p_As + 5 * TE, p_Wb + 3 * WSZ, p_Ws + 3 * WSZ, bts,  p_ct, 0);
    gemm_bf16<<<dim3(M_ROWS / 128, 1), 256, GEMM_SMEM>>>(p_Ab + 0 * TE, p_As + 0 * TE, p_WVb, p_WVs, bv, p_v, 1);

    // 5. RoPE (emits split bf16 q/k) + V operand prep
    rope_kernel<<<PROJ_ELEMS / 256, 256>>>();
    vprep_kernel<<<dim3(B_, 16), 256>>>();

    // 6. attention (bf16x3 QK^T + fp32 softmax + packed bf16 MMA PV)
    dim3 ga(L_ / QT, H_, B_);
    attn_kernel<<<ga, 256, ATTN_SMEM>>>(attn_out);

    // 7. out = mean_h(head) @ Wh
    out_kernel<<<M_ROWS / 8, 256, 64 * 512 * 4>>>(Wh, out);
}

// round 13
// speedup vs baseline: 2.1564x; 1.0243x over previous
#include <cuda_runtime.h>
#include <cuda_bf16.h>
#include <cstdint>

// Problem constants
#define B_   16
#define L_   1024
#define D_   512
#define H_   8
#define DK_  64
#define M_ROWS   (B_ * L_)            // 16384
#define TOK_ELEMS  (B_ * L_ * D_)     // 8388608
#define PROJ_ELEMS (B_ * H_ * L_ * DK_) // 8388608
#define OUT0_ELEMS ((size_t)B_ * L_ * D_)

// ---------------- scratch (device globals) ------------------------------------
// split activations (bf16 big/small): 0=sat_ln 1=ts_ln 2=satpos0 3=satpos1 4=tspos0 5=tspos1
__device__ __nv_bfloat16 g_Ab[6][TOK_ELEMS];
__device__ __nv_bfloat16 g_As[6][TOK_ELEMS];
// split transposed weights (K-major rows of 512): 0=Wq 1=Wk 2=Wsat 3=Wts
__device__ __nv_bfloat16 g_Wb[4][H_ * DK_ * D_];
__device__ __nv_bfloat16 g_Ws[4][H_ * DK_ * D_];
__device__ __nv_bfloat16 g_WVb[DK_ * D_];
__device__ __nv_bfloat16 g_WVs[DK_ * D_];

__device__ float g_ss[PROJ_ELEMS];
__device__ float g_cs[PROJ_ELEMS];
__device__ float g_st[PROJ_ELEMS];
__device__ float g_ct[PROJ_ELEMS];
__device__ float g_v[B_ * L_ * DK_];
__device__ float g_head[PROJ_ELEMS];
// post-RoPE q/k as split bf16 (big + small) for tensor-core QK^T
__device__ __nv_bfloat16 g_qb[PROJ_ELEMS];
__device__ __nv_bfloat16 g_qs[PROJ_ELEMS];
__device__ __nv_bfloat16 g_kb[PROJ_ELEMS];
__device__ __nv_bfloat16 g_ks[PROJ_ELEMS];
// V^T packed operands: per (b,d) row of 1024 uint32; Vdup=(vb,vb), Vcmp=(vs,0)
__device__ uint32_t g_vd[B_ * DK_ * L_];
__device__ uint32_t g_vc[B_ * DK_ * L_];

// ---------------- PTX helpers --------------------------------------------------
__device__ __forceinline__ uint32_t smem_u32(const void* p) {
    uint32_t a;
    asm("{ .reg .u64 t; cvta.to.shared.u64 t, %1; cvt.u32.u64 %0, t; }" : "=r"(a) : "l"(p));
    return a;
}
#define CP_ASYNC16(dst, src) \
    asm volatile("cp.async.cg.shared.global [%0], [%1], 16;" :: "r"(dst), "l"(src) : "memory")
#define CP_COMMIT() asm volatile("cp.async.commit_group;" ::: "memory")
#define CP_WAIT0()  asm volatile("cp.async.wait_group 0;" ::: "memory")
#define CP_WAIT1()  asm volatile("cp.async.wait_group 1;" ::: "memory")

#define LDSM_X4(r0, r1, r2, r3, addr) \
    asm volatile("ldmatrix.sync.aligned.m8n8.x4.shared.b16 {%0,%1,%2,%3}, [%4];" \
        : "=r"(r0), "=r"(r1), "=r"(r2), "=r"(r3) : "r"(addr))

#define MMA_BF16(c, a0, a1, a2, a3, b0, b1) \
    asm volatile("mma.sync.aligned.m16n8k16.row.col.f32.bf16.bf16.f32 " \
        "{%0,%1,%2,%3},{%4,%5,%6,%7},{%8,%9},{%0,%1,%2,%3};" \
        : "+f"((c)[0]), "+f"((c)[1]), "+f"((c)[2]), "+f"((c)[3]) \
        : "r"(a0), "r"(a1), "r"(a2), "r"(a3), "r"(b0), "r"(b1))

__device__ __forceinline__ void bf16_split(float x, __nv_bfloat16& big, __nv_bfloat16& sml) {
    big = __float2bfloat16_rn(x);
    sml = __float2bfloat16_rn(x - __bfloat162float(big));
}
__device__ __forceinline__ uint16_t bf_bits(__nv_bfloat16 v) {
    uint16_t u; *(__nv_bfloat16*)&u = v; return u;
}
__device__ __forceinline__ uint32_t bf_pack(__nv_bfloat16 lo, __nv_bfloat16 hi) {
    return (uint32_t)bf_bits(lo) | ((uint32_t)bf_bits(hi) << 16);
}

// ---------------- LayerNorm (emits split bf16) ---------------------------------
__global__ void ln_kernel(const float* __restrict__ sat, const float* __restrict__ ts,
                          const float* __restrict__ gs, const float* __restrict__ bs,
                          const float* __restrict__ gt, const float* __restrict__ bt)
{
    int rid = blockIdx.x;
    const float* src; __nv_bfloat16 *db, *ds; const float* g; const float* bb;
    if (rid < M_ROWS) {
        src = sat + (size_t)rid * D_;
        db = g_Ab[0] + (size_t)rid * D_;  ds = g_As[0] + (size_t)rid * D_;
        g = gs; bb = bs;
    } else {
        int r = rid - M_ROWS;
        src = ts + (size_t)r * D_;
        db = g_Ab[1] + (size_t)r * D_;    ds = g_As[1] + (size_t)r * D_;
        g = gt; bb = bt;
    }
    int t = threadIdx.x;
    float4 x = ((const float4*)src)[t];
    float s  = x.x + x.y + x.z + x.w;
    float sq = x.x*x.x + x.y*x.y + x.z*x.z + x.w*x.w;
    #pragma unroll
    for (int o = 16; o; o >>= 1) {
        s  += __shfl_xor_sync(0xFFFFFFFFu, s,  o);
        sq += __shfl_xor_sync(0xFFFFFFFFu, sq, o);
    }
    __shared__ float ws[4], wq[4];
    if ((t & 31) == 0) { ws[t >> 5] = s; wq[t >> 5] = sq; }
    __syncthreads();
    s  = ws[0] + ws[1] + ws[2] + ws[3];
    sq = wq[0] + wq[1] + wq[2] + wq[3];
    float m   = s * (1.0f / D_);
    float var = sq * (1.0f / D_) - m * m;
    float inv = rsqrtf(var + 1e-5f);
    float4 g4 = ((const float4*)g)[t];
    float4 b4 = ((const float4*)bb)[t];
    float o[4];
    o[0] = (x.x - m) * inv * g4.x + b4.x;
    o[1] = (x.y - m) * inv * g4.y + b4.y;
    o[2] = (x.z - m) * inv * g4.z + b4.z;
    o[3] = (x.w - m) * inv * g4.w + b4.w;
    __nv_bfloat16 big[4], sml[4];
    #pragma unroll
    for (int i = 0; i < 4; i++) bf16_split(o[i], big[i], sml[i]);
    *(uint2*)&db[t * 4] = *(uint2*)big;
    *(uint2*)&ds[t * 4] = *(uint2*)sml;
}

// ---------------- merged split (all 4 pos-embedding tensors) -------------------
__global__ void split4_kernel(const float* __restrict__ x0, const float* __restrict__ x1,
                              const float* __restrict__ x2, const float* __restrict__ x3)
{
    int which = blockIdx.y;
    const float* x = (which == 0) ? x0 : (which == 1) ? x1 : (which == 2) ? x2 : x3;
    __nv_bfloat16* big = g_Ab[2 + which];
    __nv_bfloat16* sml = g_As[2 + which];
    int i = blockIdx.x * blockDim.x + threadIdx.x;
    float4 v = ((const float4*)x)[i];
    __nv_bfloat16 b[4], s[4];
    bf16_split(v.x, b[0], s[0]);
    bf16_split(v.y, b[1], s[1]);
    bf16_split(v.z, b[2], s[2]);
    bf16_split(v.w, b[3], s[3]);
    *(uint2*)&big[(size_t)i * 4] = *(uint2*)b;
    *(uint2*)&sml[(size_t)i * 4] = *(uint2*)s;
}

// ---------------- weight transpose + split: (Hn,512,64) -> (Hn,64,512) ---------
__global__ void transpose_w(const float* __restrict__ W,
                            __nv_bfloat16* __restrict__ Wb, __nv_bfloat16* __restrict__ Wsml)
{
    __shared__ float t[64][65];
    int h = blockIdx.x, k0 = blockIdx.y * 64;
    const float* Wp = W + (size_t)h * (D_ * DK_);
    #pragma unroll
    for (int i = 0; i < 16; i++) {
        int e = threadIdx.x + i * 256;
        int r = e >> 6, c = e & 63;
        t[r][c] = Wp[(size_t)(k0 + r) * 64 + c];
    }
    __syncthreads();
    #pragma unroll
    for (int i = 0; i < 16; i++) {
        int e = threadIdx.x + i * 256;
        int n = e >> 6, kk = e & 63;
        __nv_bfloat16 big, sml;
        bf16_split(t[kk][n], big, sml);
        size_t off = (size_t)h * (DK_ * D_) + (size_t)n * 512 + k0 + kk;
        Wb[off] = big;
        Wsml[off] = sml;
    }
}

// ---------------- V prep: build packed V^T operands ----------------------------
__global__ void vprep_kernel()
{
    __shared__ float t[64][65];
    int b = blockIdx.x, k0 = blockIdx.y * 64;
    int tid = threadIdx.x;
    #pragma unroll
    for (int i = 0; i < 16; i++) {
        int e = tid + i * 256;
        int k = e >> 6, d = e & 63;
        t[k][d] = g_v[((size_t)b * L_ + k0 + k) * 64 + d];
    }
    __syncthreads();
    #pragma unroll
    for (int i = 0; i < 16; i++) {
        int e = tid + i * 256;
        int d = e >> 6, k = e & 63;
        __nv_bfloat16 vb, vs;
        bf16_split(t[k][d], vb, vs);
        size_t off = ((size_t)b * DK_ + d) * L_ + k0 + k;
        uint32_t ub = bf_bits(vb), us = bf_bits(vs);
        g_vd[off] = ub | (ub << 16);
        g_vc[off] = us;
    }
}

// ---------------- 3xBF16 projection GEMM (stride-144 packed rows) ---------------
// mode 0: write fp32 to C (head layout). mode 1: V (row-major fp32).
// mode 2: RoPE epilogue — read cosA/sinA (head layout fp32), rotate, write split
//         bf16 to outB/outS.
#define GSTR 144
#define GA_SZ (128 * GSTR)
#define GB_SZ (64 * GSTR)
#define GSTG (GA_SZ + GB_SZ)
#define GEMM_SMEM (2 * GSTG)             // 55296

__global__ void __launch_bounds__(256) gemm_bf16(const __nv_bfloat16* __restrict__ Ab,
                                                 const __nv_bfloat16* __restrict__ As,
                                                 const __nv_bfloat16* __restrict__ Bb,
                                                 const __nv_bfloat16* __restrict__ Bs,
                                                 const float* __restrict__ bias,
                                                 float* __restrict__ C,
                                                 const float* __restrict__ cosA,
                                                 const float* __restrict__ sinA,
                                                 __nv_bfloat16* __restrict__ outB,
                                                 __nv_bfloat16* __restrict__ outS,
                                                 int mode)
{
    extern __shared__ __align__(16) char smraw[];
    uint32_t sb = smem_u32(smraw);
    int tid = threadIdx.x, lane = tid & 31, wid = tid >> 5;
    int warp_m = wid >> 1, warp_n = wid & 1;
    int m0 = blockIdx.x * 128, by = blockIdx.y, n0 = by * 64;

    uint32_t laneA = (uint32_t)((warp_m * 32 + (lane & 7) + ((lane >> 3) & 1) * 8) * GSTR + (lane >> 4) * 16);
    uint32_t laneB = (uint32_t)((warp_n * 32 + (lane & 7) + ((lane >> 3) & 1) * 8) * GSTR + (lane >> 4) * 16);

    float c[8][4];
    #pragma unroll
    for (int i = 0; i < 8; i++)
        #pragma unroll
        for (int j = 0; j < 4; j++) c[i][j] = 0.0f;

    auto load_stage = [&](int s, int k0) {
        uint32_t base = sb + s * GSTG;
        #pragma unroll
        for (int i = 0; i < 4; i++) {
            int e = tid + i * 256, r = e >> 3, cc = e & 7;
            const __nv_bfloat16* src = (cc < 4)
                ? Ab + (size_t)(m0 + r) * 512 + k0 + cc * 8
                : As + (size_t)(m0 + r) * 512 + k0 + (cc - 4) * 8;
            CP_ASYNC16(base + (uint32_t)(r * GSTR + cc * 16), src);
        }
        #pragma unroll
        for (int i = 0; i < 2; i++) {
            int e = tid + i * 256, r = e >> 3, cc = e & 7;
            const __nv_bfloat16* src = (cc < 4)
                ? Bb + (size_t)(n0 + r) * 512 + k0 + cc * 8
                : Bs + (size_t)(n0 + r) * 512 + k0 + (cc - 4) * 8;
            CP_ASYNC16(base + GA_SZ + (uint32_t)(r * GSTR + cc * 16), src);
        }
    };

    auto compute = [&](int s) {
        uint32_t abase = sb + s * GSTG + laneA;
        uint32_t bbase = sb + s * GSTG + GA_SZ + laneB;
        #pragma unroll
        for (int ks = 0; ks < 2; ks++) {
            uint32_t aB[2][4], aS[2][4], bB[2][4], bS[2][4];
            #pragma unroll
            for (int mt = 0; mt < 2; mt++) {
                LDSM_X4(aB[mt][0], aB[mt][1], aB[mt][2], aB[mt][3], abase + mt * (16 * GSTR) + ks * 32);
                LDSM_X4(aS[mt][0], aS[mt][1], aS[mt][2], aS[mt][3], abase + mt * (16 * GSTR) + 64 + ks * 32);
            }
            #pragma unroll
            for (int nt = 0; nt < 2; nt++) {
                LDSM_X4(bB[nt][0], bB[nt][1], bB[nt][2], bB[nt][3], bbase + nt * (16 * GSTR) + ks * 32);
                LDSM_X4(bS[nt][0], bS[nt][1], bS[nt][2], bS[nt][3], bbase + nt * (16 * GSTR) + 64 + ks * 32);
            }
            #pragma unroll
            for (int mt = 0; mt < 2; mt++)
                #pragma unroll
                for (int j = 0; j < 4; j++) {
                    int nt = j >> 1, hh = j & 1;
                    float* cc = c[mt * 4 + j];
                    MMA_BF16(cc, aS[mt][0], aS[mt][1], aS[mt][2], aS[mt][3], bB[nt][hh], bB[nt][2 + hh]);
                    MMA_BF16(cc, aB[mt][0], aB[mt][1], aB[mt][2], aB[mt][3], bS[nt][hh], bS[nt][2 + hh]);
                    MMA_BF16(cc, aB[mt][0], aB[mt][1], aB[mt][2], aB[mt][3], bB[nt][hh], bB[nt][2 + hh]);
                }
        }
    };

    load_stage(0, 0);
    CP_COMMIT();
    for (int ck = 0; ck < 16; ck++) {
        if (ck < 15) {
            load_stage((ck + 1) & 1, (ck + 1) * 32);
            CP_COMMIT();
            CP_WAIT1();
        } else {
            CP_WAIT0();
        }
        __syncthreads();
        compute(ck & 1);
        __syncthreads();
    }

    int r_lane = lane >> 2, c_lane = (lane & 3) * 2;
    #pragma unroll
    for (int i = 0; i < 2; i++) {
        #pragma unroll
        for (int j = 0; j < 4; j++) {
            float* cc = c[i * 4 + j];
            int nc = warp_n * 32 + j * 8 + c_lane;           // even
            int mrow = m0 + warp_m * 32 + i * 16 + r_lane;
            float2 bb2;
            size_t base0, base1;
            if (mode == 1) {
                bb2 = *(const float2*)&bias[nc];
                base0 = (size_t)mrow * 64 + nc;
                base1 = (size_t)(mrow + 8) * 64 + nc;
            } else {
                bb2 = *(const float2*)&bias[by * 64 + nc];
                int b0r = mrow >> 10, l0r = mrow & 1023;
                int b1r = (mrow + 8) >> 10, l1r = (mrow + 8) & 1023;
                base0 = ((((size_t)(b0r * 8 + by)) << 10) + l0r) * 64 + nc;
                base1 = ((((size_t)(b1r * 8 + by)) << 10) + l1r) * 64 + nc;
            }
            float v00 = cc[0] + bb2.x, v01 = cc[1] + bb2.y;
            float v10 = cc[2] + bb2.x, v11 = cc[3] + bb2.y;
            if (mode == 2) {
                // fused RoPE: out[2j] = x0*c0 - x1*s0 ; out[2j+1] = x1*c1 + x0*s1
                float2 cv0 = *(const float2*)&cosA[base0];
                float2 sv0 = *(const float2*)&sinA[base0];
                float2 cv1 = *(const float2*)&cosA[base1];
                float2 sv1 = *(const float2*)&sinA[base1];
                float o00 = v00 * cv0.x - v01 * sv0.x;
                float o01 = v01 * cv0.y + v00 * sv0.y;
                float o10 = v10 * cv1.x - v11 * sv1.x;
                float o11 = v11 * cv1.y + v10 * sv1.y;
                __nv_bfloat16 b0, s0, b1, s1;
                bf16_split(o00, b0, s0); bf16_split(o01, b1, s1);
                *(uint32_t*)&outB[base0] = bf_pack(b0, b1);
                *(uint32_t*)&outS[base0] = bf_pack(s0, s1);
                bf16_split(o10, b0, s0); bf16_split(o11, b1, s1);
                *(uint32_t*)&outB[base1] = bf_pack(b0, b1);
                *(uint32_t*)&outS[base1] = bf_pack(s0, s1);
            } else {
                float2 o0 = {v00, v01};
                float2 o1 = {v10, v11};
                *(float2*)&C[base0] = o0;
                *(float2*)&C[base1] = o1;
            }
        }
    }
}

// ---------------- attention: bf16x3 QK^T + packed-bf16 MMA PV (proven R9/R10) ---
#define QT  32
#define KT  256
#define SCP 1028
#define STRK 144
#define STRV 528
#define SC_BYTES   (QT * SCP * 4)
#define KREG_OFF   SC_BYTES
#define KREG_BYTES (2 * KT * STRK)
#define VC_OFF     (64 * STRV)
#define QREG_OFF   (KREG_OFF + KREG_BYTES)
#define QB_BYTES   (QT * STRK)
#define ATTN_SMEM  (QREG_OFF + 2 * QB_BYTES)

__global__ void __launch_bounds__(256) attn_kernel(float* __restrict__ attn_out)
{
    extern __shared__ __align__(16) float smf[];
    float* sc  = smf;
    uint32_t* scu = (uint32_t*)smf;
    char*  kreg = (char*)smf + KREG_OFF;
    char*  qreg = (char*)smf + QREG_OFF;

    int tid = threadIdx.x, lane = tid & 31, wid = tid >> 5;
    int q0 = blockIdx.x * QT;
    int h  = blockIdx.y;
    int b  = blockIdx.z;
    size_t bh = (size_t)(b * H_ + h);

    uint32_t skb = smem_u32(kreg), sqb = smem_u32(qreg), ssb = smem_u32(sc);

    {
        int r = tid >> 3, cch = tid & 7;
        const uint4* srcb = (const uint4*)&g_qb[((bh << 10) + q0 + r) * 64];
        const uint4* srcs = (const uint4*)&g_qs[((bh << 10) + q0 + r) * 64];
        *(uint4*)(qreg + r * STRK + cch * 16)            = srcb[cch];
        *(uint4*)(qreg + QB_BYTES + r * STRK + cch * 16) = srcs[cch];
    }

    uint32_t aB0 = sqb + (uint32_t)(((lane & 7) + ((lane >> 3) & 1) * 8) * STRK + (lane >> 4) * 16);
    uint32_t aS0 = aB0 + QB_BYTES;
    uint32_t bB0 = skb + (uint32_t)((wid * 32 + (lane & 7) + ((lane >> 3) & 1) * 8) * STRK + (lane >> 4) * 16);
    uint32_t bS0 = bB0 + (uint32_t)(KT * STRK);

    for (int kt = 0; kt < 4; kt++) {
        __syncthreads();
        size_t kbase = ((bh << 10) + kt * KT) * 64;
        #pragma unroll
        for (int i = 0; i < 8; i++) {
            int e = tid + i * 256, r = e >> 3, cch = e & 7;
            const uint4* srcb = (const uint4*)&g_kb[kbase + (size_t)r * 64];
            const uint4* srcs = (const uint4*)&g_ks[kbase + (size_t)r * 64];
            *(uint4*)(kreg + r * STRK + cch * 16)             = srcb[cch];
            *(uint4*)(kreg + KT * STRK + r * STRK + cch * 16) = srcs[cch];
        }
        __syncthreads();

        float c[2][4][4];
        #pragma unroll
        for (int mt = 0; mt < 2; mt++)
            #pragma unroll
            for (int j = 0; j < 4; j++)
                #pragma unroll
                for (int e = 0; e < 4; e++) c[mt][j][e] = 0.0f;

        #pragma unroll
        for (int ks = 0; ks < 4; ks++) {
            uint32_t aB[2][4], aS[2][4], bB[2][4], bS[2][4];
            #pragma unroll
            for (int mt = 0; mt < 2; mt++) {
                LDSM_X4(aB[mt][0], aB[mt][1], aB[mt][2], aB[mt][3], aB0 + mt * (16 * STRK) + ks * 32);
                LDSM_X4(aS[mt][0], aS[mt][1], aS[mt][2], aS[mt][3], aS0 + mt * (16 * STRK) + ks * 32);
            }
            #pragma unroll
            for (int nt = 0; nt < 2; nt++) {
                LDSM_X4(bB[nt][0], bB[nt][1], bB[nt][2], bB[nt][3], bB0 + nt * (16 * STRK) + ks * 32);
                LDSM_X4(bS[nt][0], bS[nt][1], bS[nt][2], bS[nt][3], bS0 + nt * (16 * STRK) + ks * 32);
            }
            #pragma unroll
            for (int mt = 0; mt < 2; mt++)
                #pragma unroll
                for (int j = 0; j < 4; j++) {
                    int nt = j >> 1, hh = j & 1;
                    float* cc = c[mt][j];
                    MMA_BF16(cc, aS[mt][0], aS[mt][1], aS[mt][2], aS[mt][3], bB[nt][hh], bB[nt][2 + hh]);
                    MMA_BF16(cc, aB[mt][0], aB[mt][1], aB[mt][2], aB[mt][3], bS[nt][hh], bS[nt][2 + hh]);
                    MMA_BF16(cc, aB[mt][0], aB[mt][1], aB[mt][2], aB[mt][3], bB[nt][hh], bB[nt][2 + hh]);
                }
        }
        int rr = lane >> 2, ccl = (lane & 3) * 2;
        #pragma unroll
        for (int mt = 0; mt < 2; mt++)
            #pragma unroll
            for (int j = 0; j < 4; j++) {
                int col = kt * KT + wid * 32 + j * 8 + ccl;
                int row0 = mt * 16 + rr;
                float2 o0 = {c[mt][j][0] * 0.125f, c[mt][j][1] * 0.125f};
                float2 o1 = {c[mt][j][2] * 0.125f, c[mt][j][3] * 0.125f};
                *(float2*)&sc[row0 * SCP + col]       = o0;
                *(float2*)&sc[(row0 + 8) * SCP + col] = o1;
            }
    }
    __syncthreads();

    for (int rr = wid * 4; rr < wid * 4 + 4; rr++) {
        float vals[32];
        float mx = -1e30f;
        #pragma unroll
        for (int j = 0; j < 32; j++) {
            vals[j] = sc[rr * SCP + lane + 32 * j];
            mx = fmaxf(mx, vals[j]);
        }
        #pragma unroll
        for (int o = 16; o; o >>= 1) mx = fmaxf(mx, __shfl_xor_sync(0xFFFFFFFFu, mx, o));
        float s = 0.0f;
        #pragma unroll
        for (int j = 0; j < 32; j++) { vals[j] = __expf(vals[j] - mx); s += vals[j]; }
        #pragma unroll
        for (int o = 16; o; o >>= 1) s += __shfl_xor_sync(0xFFFFFFFFu, s, o);
        float inv = 1.0f / s;
        size_t obase = (((size_t)(b * L_ + q0 + rr) * H_ + h) << 10);
        #pragma unroll
        for (int j = 0; j < 32; j++) {
            float p = vals[j] * inv;
            attn_out[obase + lane + 32 * j] = p;
            __nv_bfloat16 pb, ps;
            bf16_split(p, pb, ps);
            scu[rr * SCP + lane + 32 * j] = bf_pack(pb, ps);
        }
    }

    int mt = wid >> 2, nt = wid & 3;
    float acc[2][4];
    #pragma unroll
    for (int j = 0; j < 2; j++)
        #pragma unroll
        for (int e = 0; e < 4; e++) acc[j][e] = 0.0f;

    uint32_t aP0 = ssb + (uint32_t)((mt * 16 + (lane & 7) + ((lane >> 3) & 1) * 8) * (SCP * 4) + (lane >> 4) * 16);
    uint32_t vD0 = skb + (uint32_t)((nt * 16 + (lane & 7) + ((lane >> 3) & 1) * 8) * STRV + (lane >> 4) * 16);
    uint32_t vC0 = vD0 + (uint32_t)VC_OFF;

    for (int vt = 0; vt < 8; vt++) {
        __syncthreads();
        {
            const uint32_t* vdg = g_vd + ((size_t)b * DK_) * L_ + vt * 128;
            const uint32_t* vcg = g_vc + ((size_t)b * DK_) * L_ + vt * 128;
            #pragma unroll
            for (int i = 0; i < 8; i++) {
                int e = tid + i * 256, r = e >> 5, ch = e & 31;
                *(uint4*)(kreg + r * STRV + ch * 16)          = *(const uint4*)(vdg + (size_t)r * L_ + ch * 4);
                *(uint4*)(kreg + VC_OFF + r * STRV + ch * 16) = *(const uint4*)(vcg + (size_t)r * L_ + ch * 4);
            }
        }
        __syncthreads();
        #pragma unroll
        for (int st = 0; st < 16; st++) {
            uint32_t a[4], bd[4], bc[4];
            LDSM_X4(a[0], a[1], a[2], a[3], aP0 + (uint32_t)(vt * 512 + st * 32));
            LDSM_X4(bd[0], bd[1], bd[2], bd[3], vD0 + st * 32);
            LDSM_X4(bc[0], bc[1], bc[2], bc[3], vC0 + st * 32);
            #pragma unroll
            for (int j = 0; j < 2; j++) {
                MMA_BF16(acc[j], a[0], a[1], a[2], a[3], bd[j], bd[2 + j]);
                MMA_BF16(acc[j], a[0], a[1], a[2], a[3], bc[j], bc[2 + j]);
            }
        }
    }
    {
        int rr = lane >> 2, cl = (lane & 3) * 2;
        #pragma unroll
        for (int j = 0; j < 2; j++) {
            int col = nt * 16 + j * 8 + cl;
            int row0 = mt * 16 + rr;
            float2 o0 = {acc[j][0], acc[j][1]};
            float2 o1 = {acc[j][2], acc[j][3]};
            *(float2*)&g_head[((bh << 10) + q0 + row0) * 64 + col]     = o0;
            *(float2*)&g_head[((bh << 10) + q0 + row0 + 8) * 64 + col] = o1;
        }
    }
}

// ---------------- final: out = mean_h(head) @ Wh ------------------------------
__global__ void __launch_bounds__(256) out_kernel(const float* __restrict__ Wh,
                                                  float* __restrict__ out)
{
    extern __shared__ __align__(16) float sm2[];
    __shared__ float hm[8][64];
    int tid = threadIdx.x;
    int m0 = blockIdx.x * 8;
    int bb = m0 >> 10;
    int l0 = m0 & 1023;

    #pragma unroll
    for (int i = 0; i < 32; i++) {
        int e = tid + i * 256;
        ((float4*)sm2)[e] = ((const float4*)Wh)[e];
    }
    #pragma unroll
    for (int i = 0; i < 2; i++) {
        int e = tid + i * 256;
        int r = e >> 6, kk = e & 63;
        float s = 0.0f;
        #pragma unroll
        for (int hh = 0; hh < 8; hh++)
            s += g_head[(((size_t)(bb * H_ + hh) << 10) + l0 + r) * 64 + kk];
        hm[r][kk] = s * 0.125f;
    }
    __syncthreads();

    int ty = tid >> 6;
    int tx = tid & 63;
    float acc[2][8];
    #pragma unroll
    for (int i = 0; i < 2; i++)
        #pragma unroll
        for (int j = 0; j < 8; j++) acc[i][j] = 0.0f;
    #pragma unroll 8
    for (int d = 0; d < 64; d++) {
        float a0 = hm[ty * 2][d];
        float a1 = hm[ty * 2 + 1][d];
        float4 w0 = *(float4*)&sm2[d * 512 + tx * 8];
        float4 w1 = *(float4*)&sm2[d * 512 + tx * 8 + 4];
        acc[0][0] += a0 * w0.x; acc[0][1] += a0 * w0.y; acc[0][2] += a0 * w0.z; acc[0][3] += a0 * w0.w;
        acc[0][4] += a0 * w1.x; acc[0][5] += a0 * w1.y; acc[0][6] += a0 * w1.z; acc[0][7] += a0 * w1.w;
        acc[1][0] += a1 * w0.x; acc[1][1] += a1 * w0.y; acc[1][2] += a1 * w0.z; acc[1][3] += a1 * w0.w;
        acc[1][4] += a1 * w1.x; acc[1][5] += a1 * w1.y; acc[1][6] += a1 * w1.z; acc[1][7] += a1 * w1.w;
    }
    #pragma unroll
    for (int i = 0; i < 2; i++) {
        int m = m0 + ty * 2 + i;
        float4 o0 = {acc[i][0], acc[i][1], acc[i][2], acc[i][3]};
        float4 o1 = {acc[i][4], acc[i][5], acc[i][6], acc[i][7]};
        *(float4*)&out[(size_t)m * 512 + tx * 8]     = o0;
        *(float4*)&out[(size_t)m * 512 + tx * 8 + 4] = o1;
    }
}

// ---------------- launch ------------------------------------------------------
extern "C" void kernel_launch(void* const* d_in, const int* in_sizes, int n_in,
                              void* d_out, int out_size)
{
    const float* sat     = (const float*)d_in[0];
    const float* satpos  = (const float*)d_in[1];
    const float* ts      = (const float*)d_in[2];
    const float* tspos   = (const float*)d_in[3];
    const float* lsg     = (const float*)d_in[4];
    const float* lsb     = (const float*)d_in[5];
    const float* ltg     = (const float*)d_in[6];
    const float* ltb     = (const float*)d_in[7];
    const float* Wv      = (const float*)d_in[8];
    const float* bv      = (const float*)d_in[9];
    const float* Wq      = (const float*)d_in[10];
    const float* bq      = (const float*)d_in[11];
    const float* Wk      = (const float*)d_in[12];
    const float* bk      = (const float*)d_in[13];
    const float* Wsat    = (const float*)d_in[14];
    const float* bsat    = (const float*)d_in[15];
    const float* Wts     = (const float*)d_in[16];
    const float* bts     = (const float*)d_in[17];
    const float* Wh      = (const float*)d_in[18];

    float* out      = (float*)d_out;
    float* attn_out = out + OUT0_ELEMS;

    float *p_ss, *p_cs, *p_st, *p_ct, *p_v;
    __nv_bfloat16 *p_Ab, *p_As, *p_Wb, *p_Ws, *p_WVb, *p_WVs;
    __nv_bfloat16 *p_qb, *p_qs, *p_kb, *p_ks;
    cudaGetSymbolAddress((void**)&p_ss,  g_ss);
    cudaGetSymbolAddress((void**)&p_cs,  g_cs);
    cudaGetSymbolAddress((void**)&p_st,  g_st);
    cudaGetSymbolAddress((void**)&p_ct,  g_ct);
    cudaGetSymbolAddress((void**)&p_v,   g_v);
    cudaGetSymbolAddress((void**)&p_Ab,  g_Ab);
    cudaGetSymbolAddress((void**)&p_As,  g_As);
    cudaGetSymbolAddress((void**)&p_Wb,  g_Wb);
    cudaGetSymbolAddress((void**)&p_Ws,  g_Ws);
    cudaGetSymbolAddress((void**)&p_WVb, g_WVb);
    cudaGetSymbolAddress((void**)&p_WVs, g_WVs);
    cudaGetSymbolAddress((void**)&p_qb,  g_qb);
    cudaGetSymbolAddress((void**)&p_qs,  g_qs);
    cudaGetSymbolAddress((void**)&p_kb,  g_kb);
    cudaGetSymbolAddress((void**)&p_ks,  g_ks);

    cudaFuncSetAttribute(attn_kernel, cudaFuncAttributeMaxDynamicSharedMemorySize, ATTN_SMEM);
    cudaFuncSetAttribute(out_kernel,  cudaFuncAttributeMaxDynamicSharedMemorySize, 64 * 512 * 4);
    cudaFuncSetAttribute(gemm_bf16,   cudaFuncAttributeMaxDynamicSharedMemorySize, GEMM_SMEM);

    const size_t WSZ = (size_t)H_ * DK_ * D_;
    const size_t TE  = (size_t)TOK_ELEMS;

    // 1. LayerNorms (emit split bf16)
    ln_kernel<<<2 * M_ROWS, 128>>>(sat, ts, lsg, lsb, ltg, ltb);

    // 2. split pos embeddings (one launch)
    split4_kernel<<<dim3(TOK_ELEMS / 1024, 4), 256>>>(satpos, satpos + TOK_ELEMS,
                                                      tspos, tspos + TOK_ELEMS);

    // 3. transpose + split weights
    transpose_w<<<dim3(8, 8), 256>>>(Wq,   p_Wb + 0 * WSZ, p_Ws + 0 * WSZ);
    transpose_w<<<dim3(8, 8), 256>>>(Wk,   p_Wb + 1 * WSZ, p_Ws + 1 * WSZ);
    transpose_w<<<dim3(8, 8), 256>>>(Wsat, p_Wb + 2 * WSZ, p_Ws + 2 * WSZ);
    transpose_w<<<dim3(8, 8), 256>>>(Wts,  p_Wb + 3 * WSZ, p_Ws + 3 * WSZ);
    transpose_w<<<dim3(1, 8), 256>>>(Wv,   p_WVb, p_WVs);

    // 4. sin/cos projections first (plain fp32 out)
    dim3 gg(M_ROWS / 128, 8);
    gemm_bf16<<<gg, 256, GEMM_SMEM>>>(p_Ab + 2 * TE, p_As + 2 * TE, p_Wb + 2 * WSZ, p_Ws + 2 * WSZ, bsat, p_ss, nullptr, nullptr, nullptr, nullptr, 0);
    gemm_bf16<<<gg, 256, GEMM_SMEM>>>(p_Ab + 3 * TE, p_As + 3 * TE, p_Wb + 2 * WSZ, p_Ws + 2 * WSZ, bsat, p_cs, nullptr, nullptr, nullptr, nullptr, 0);
    gemm_bf16<<<gg, 256, GEMM_SMEM>>>(p_Ab + 4 * TE, p_As + 4 * TE, p_Wb + 3 * WSZ, p_Ws + 3 * WSZ, bts,  p_st, nullptr, nullptr, nullptr, nullptr, 0);
    gemm_bf16<<<gg, 256, GEMM_SMEM>>>(p_Ab + 5 * TE, p_As + 5 * TE, p_Wb + 3 * WSZ, p_Ws + 3 * WSZ, bts,  p_ct, nullptr, nullptr, nullptr, nullptr, 0);

    // 5. q/k projections with fused RoPE epilogue -> split bf16
    gemm_bf16<<<gg, 256, GEMM_SMEM>>>(p_Ab + 1 * TE, p_As + 1 * TE, p_Wb + 0 * WSZ, p_Ws + 0 * WSZ, bq, nullptr, p_ct, p_st, p_qb, p_qs, 2);
    gemm_bf16<<<gg, 256, GEMM_SMEM>>>(p_Ab + 0 * TE, p_As + 0 * TE, p_Wb + 1 * WSZ, p_Ws + 1 * WSZ, bk, nullptr, p_cs, p_ss, p_kb, p_ks, 2);

    // 6. V projection + packed V^T operands
    gemm_bf16<<<dim3(M_ROWS / 128, 1), 256, GEMM_SMEM>>>(p_Ab + 0 * TE, p_As + 0 * TE, p_WVb, p_WVs, bv, p_v, nullptr, nullptr, nullptr, nullptr, 1);
    vprep_kernel<<<dim3(B_, 16), 256>>>();

    // 7. attention (bf16x3 QK^T + fp32 softmax + packed bf16 MMA PV)
    dim3 ga(L_ / QT, H_, B_);
    attn_kernel<<<ga, 256, ATTN_SMEM>>>(attn_out);

    // 8. out = mean_h(head) @ Wh
    out_kernel<<<M_ROWS / 8, 256, 64 * 512 * 4>>>(Wh, out);
}